// round 1
// baseline (speedup 1.0000x reference)
#include <cuda_runtime.h>
#include <cstddef>

// Problem constants (fixed by the reference)
#define BB   2
#define NN   50000
#define EE   150000
#define FF   256
#define OUTD 256
#define RR   (BB * NN)      // 100000 rows
#define KTOT (3 * FF)       // 768

// Scratch: [r][0:256]=mi, [r][256:512]=mo  (rows r = b*NN + n)
__device__ float g_agg[(size_t)RR * 512];
// Hidden activations h = tanh(M @ W1 + b1)
__device__ float g_h[(size_t)RR * OUTD];

// ---------------------------------------------------------------------------
// Kernel 1: zero the aggregation scratch
// ---------------------------------------------------------------------------
__global__ void zero_agg_kernel() {
    size_t i = (size_t)blockIdx.x * blockDim.x + threadIdx.x;
    const size_t total = (size_t)RR * 512 / 4;
    float4 z = make_float4(0.f, 0.f, 0.f, 0.f);
    float4* p = reinterpret_cast<float4*>(g_agg);
    for (; i < total; i += (size_t)gridDim.x * blockDim.x) p[i] = z;
}

// ---------------------------------------------------------------------------
// Kernel 2: edge scatter. One warp per (batch, edge); handles both directions.
//   mi[ri[k]] += w[k] * X[ro[k]]
//   mo[ro[k]] += w[k] * X[ri[k]]
// Vector f32x4 global reductions (sm_90+) to quarter the atomic op count.
// ---------------------------------------------------------------------------
__device__ __forceinline__ void red_add_v4(float* p, float4 v) {
    asm volatile("red.global.add.v4.f32 [%0], {%1, %2, %3, %4};"
                 :: "l"(p), "f"(v.x), "f"(v.y), "f"(v.z), "f"(v.w)
                 : "memory");
}

__global__ void __launch_bounds__(256) scatter_kernel(
    const float* __restrict__ X,
    const float* __restrict__ e,
    const int*   __restrict__ ri_idx,
    const int*   __restrict__ ro_idx)
{
    int task = blockIdx.x * (blockDim.x >> 5) + (threadIdx.x >> 5);
    int lane = threadIdx.x & 31;
    if (task >= BB * EE) return;

    int b  = task / EE;
    int ed = task - b * EE;
    int gi = b * EE + ed;

    float w = e[gi];
    int ri = ri_idx[gi];
    int ro = ro_idx[gi];

    const float4* xro = reinterpret_cast<const float4*>(X + ((size_t)b * NN + ro) * FF);
    const float4* xri = reinterpret_cast<const float4*>(X + ((size_t)b * NN + ri) * FF);
    float* mi_row = g_agg + ((size_t)b * NN + ri) * 512;        // mi dest
    float* mo_row = g_agg + ((size_t)b * NN + ro) * 512 + 256;  // mo dest

    #pragma unroll
    for (int t = 0; t < 2; t++) {
        int idx = lane + t * 32;            // float4 index 0..63
        float4 a = xro[idx];
        a.x *= w; a.y *= w; a.z *= w; a.w *= w;
        red_add_v4(mi_row + idx * 4, a);

        float4 c = xri[idx];
        c.x *= w; c.y *= w; c.z *= w; c.w *= w;
        red_add_v4(mo_row + idx * 4, c);
    }
}

// ---------------------------------------------------------------------------
// Kernel 3/4: tiled fp32 GEMM + bias + tanh.
//   C[rows x 256] = tanh( A[rows x Ktot] @ W[Ktot x 256] + bias )
// A is split into two row-major regions: cols [0, ka0) from A0 (ld lda0),
// cols [ka0, Ktot) from A1 (ld lda1). BK=16 divides the split (512), so each
// k-tile lives entirely in one region.
// Tile: BM=64, BN=64, BK=16, 256 threads, 4x4 microtile per thread.
// ---------------------------------------------------------------------------
#define BM 64
#define BN 64
#define BK 16

__global__ void __launch_bounds__(256) mlp_gemm_kernel(
    const float* __restrict__ A0, int lda0, int ka0,
    const float* __restrict__ A1, int lda1,
    const float* __restrict__ W,
    const float* __restrict__ bias,
    float* __restrict__ Cout,
    int Ktot, int rows)
{
    __shared__ __align__(16) float As[BK][BM];
    __shared__ __align__(16) float Bs[BK][BN];

    const int tid = threadIdx.x;
    const int tx = tid & 15;        // 0..15 -> output col group
    const int ty = tid >> 4;        // 0..15 -> output row group
    const int rowBase = blockIdx.y * BM;
    const int colBase = blockIdx.x * BN;

    // A-load mapping: 64 rows x 16 cols, float4 per thread
    const int arow = tid >> 2;            // 0..63
    const int acol = (tid & 3) * 4;       // 0,4,8,12
    // B-load mapping: 16 rows x 64 cols, float4 per thread
    const int brow = tid >> 4;            // 0..15
    const int bcol = (tid & 15) * 4;      // 0..60

    float acc[4][4] = {};

    for (int k0 = 0; k0 < Ktot; k0 += BK) {
        float4 av;
        const int gr = rowBase + arow;
        if (gr < rows) {
            const float* ap;
            if (k0 < ka0) ap = A0 + (size_t)gr * lda0 + (k0 + acol);
            else          ap = A1 + (size_t)gr * lda1 + (k0 - ka0 + acol);
            av = *reinterpret_cast<const float4*>(ap);
        } else {
            av = make_float4(0.f, 0.f, 0.f, 0.f);
        }
        const float4 bv = *reinterpret_cast<const float4*>(
            W + (size_t)(k0 + brow) * 256 + colBase + bcol);

        __syncthreads();   // protect previous iteration's smem reads
        As[acol + 0][arow] = av.x;
        As[acol + 1][arow] = av.y;
        As[acol + 2][arow] = av.z;
        As[acol + 3][arow] = av.w;
        *reinterpret_cast<float4*>(&Bs[brow][bcol]) = bv;
        __syncthreads();

        #pragma unroll
        for (int k = 0; k < BK; k++) {
            float a[4], b[4];
            *reinterpret_cast<float4*>(a) = *reinterpret_cast<const float4*>(&As[k][ty * 4]);
            *reinterpret_cast<float4*>(b) = *reinterpret_cast<const float4*>(&Bs[k][tx * 4]);
            #pragma unroll
            for (int i = 0; i < 4; i++)
                #pragma unroll
                for (int j = 0; j < 4; j++)
                    acc[i][j] = fmaf(a[i], b[j], acc[i][j]);
        }
    }

    #pragma unroll
    for (int i = 0; i < 4; i++) {
        const int gr = rowBase + ty * 4 + i;
        if (gr < rows) {
            #pragma unroll
            for (int j = 0; j < 4; j++) {
                const int gc = colBase + tx * 4 + j;
                Cout[(size_t)gr * 256 + gc] = tanhf(acc[i][j] + bias[gc]);
            }
        }
    }
}

// ---------------------------------------------------------------------------
// Launcher
// Inputs (metadata order): X, e, ri_idx, ro_idx, W1, b1, W2, b2
// ---------------------------------------------------------------------------
extern "C" void kernel_launch(void* const* d_in, const int* in_sizes, int n_in,
                              void* d_out, int out_size)
{
    (void)in_sizes; (void)n_in; (void)out_size;

    const float* X  = (const float*)d_in[0];
    const float* e  = (const float*)d_in[1];
    const int*   ri = (const int*)  d_in[2];
    const int*   ro = (const int*)  d_in[3];
    const float* W1 = (const float*)d_in[4];
    const float* b1 = (const float*)d_in[5];
    const float* W2 = (const float*)d_in[6];
    const float* b2 = (const float*)d_in[7];
    float* out = (float*)d_out;

    float* agg_ptr = nullptr;
    float* h_ptr   = nullptr;
    cudaGetSymbolAddress((void**)&agg_ptr, g_agg);
    cudaGetSymbolAddress((void**)&h_ptr,   g_h);

    // 1. zero scratch (51.2M floats)
    zero_agg_kernel<<<8192, 256>>>();

    // 2. scatter: 300000 warps, 8 per block
    scatter_kernel<<<(BB * EE) / 8, 256>>>(X, e, ri, ro);

    // 3. GEMM1: h = tanh([mi|mo|X] @ W1 + b1)   K = 768 (512 from agg, 256 from X)
    {
        dim3 grid(256 / BN, (RR + BM - 1) / BM);
        mlp_gemm_kernel<<<grid, 256>>>(agg_ptr, 512, 512, X, 256,
                                       W1, b1, h_ptr, KTOT, RR);
    }

    // 4. GEMM2: out = tanh(h @ W2 + b2)   K = 256
    {
        dim3 grid(256 / BN, (RR + BM - 1) / BM);
        mlp_gemm_kernel<<<grid, 256>>>(h_ptr, 256, 256, nullptr, 0,
                                       W2, b2, out, 256, RR);
    }
}

// round 2
// speedup vs baseline: 1.0350x; 1.0350x over previous
#include <cuda_runtime.h>
#include <cstddef>

// Problem constants (fixed by the reference)
#define BB   2
#define NN   50000
#define EE   150000
#define FF   256
#define OUTD 256
#define RR   (BB * NN)       // 100000 rows
#define KTOT (3 * FF)        // 768
#define SEG  (4 * NN)        // 200000 segments: (b,dir) x node
#define TOTE (4 * EE)        // 600000 CSR entries

// Scratch
__device__ float g_agg[(size_t)RR * 512];   // [r][0:256]=mi, [r][256:512]=mo
__device__ float g_h[(size_t)RR * OUTD];    // hidden activations

// CSR scratch
__device__ int   g_count[SEG];
__device__ int   g_fill[SEG];
__device__ int   g_start[SEG];
__device__ int   g_bsum[128];
__device__ int   g_entry_src[TOTE];
__device__ float g_entry_w[TOTE];

#define SCAN_TILE 2048                      // 256 thr x 8 elems
#define SCAN_NB   ((SEG + SCAN_TILE - 1) / SCAN_TILE)   // 98

// ---------------------------------------------------------------------------
// CSR build
// ---------------------------------------------------------------------------
__global__ void zero_counts_kernel() {
    int i = blockIdx.x * blockDim.x + threadIdx.x;
    if (i < SEG) { g_count[i] = 0; g_fill[i] = 0; }
}

__global__ void count_kernel(const int* __restrict__ ri_idx,
                             const int* __restrict__ ro_idx) {
    int t = blockIdx.x * blockDim.x + threadIdx.x;   // (b, edge)
    if (t >= BB * EE) return;
    int b = t / EE;
    int ri = ri_idx[t];
    int ro = ro_idx[t];
    atomicAdd(&g_count[(2 * b + 0) * NN + ri], 1);   // mi segment keyed by ri
    atomicAdd(&g_count[(2 * b + 1) * NN + ro], 1);   // mo segment keyed by ro
}

// scan phase 1: per-block exclusive scan + block sums
__global__ void __launch_bounds__(256) scan1_kernel() {
    __shared__ int sh[256];
    const int base = blockIdx.x * SCAN_TILE + threadIdx.x * 8;
    int v[8]; int s = 0;
    #pragma unroll
    for (int j = 0; j < 8; j++) {
        int idx = base + j;
        int x = (idx < SEG) ? g_count[idx] : 0;
        v[j] = s;            // local exclusive prefix
        s += x;
    }
    sh[threadIdx.x] = s;
    __syncthreads();
    // Kogge-Stone inclusive scan over thread sums
    int acc = s;
    #pragma unroll
    for (int off = 1; off < 256; off <<= 1) {
        int t = (threadIdx.x >= off) ? sh[threadIdx.x - off] : 0;
        __syncthreads();
        acc += t;
        sh[threadIdx.x] = acc;
        __syncthreads();
    }
    int excl = acc - s;      // exclusive prefix of this thread within block
    #pragma unroll
    for (int j = 0; j < 8; j++) {
        int idx = base + j;
        if (idx < SEG) g_start[idx] = excl + v[j];
    }
    if (threadIdx.x == 255) g_bsum[blockIdx.x] = acc;   // block total
}

// scan phase 2: exclusive scan of block sums (single block)
__global__ void scan2_kernel() {
    __shared__ int sh[128];
    int t = threadIdx.x;
    int x = (t < SCAN_NB) ? g_bsum[t] : 0;
    sh[t] = x;
    __syncthreads();
    int acc = x;
    #pragma unroll
    for (int off = 1; off < 128; off <<= 1) {
        int y = (t >= off) ? sh[t - off] : 0;
        __syncthreads();
        acc += y;
        sh[t] = acc;
        __syncthreads();
    }
    if (t < SCAN_NB) g_bsum[t] = acc - x;   // exclusive
}

// scan phase 3: add block offsets
__global__ void __launch_bounds__(256) scan3_kernel() {
    int off = g_bsum[blockIdx.x];
    int base = blockIdx.x * SCAN_TILE + threadIdx.x * 8;
    #pragma unroll
    for (int j = 0; j < 8; j++) {
        int idx = base + j;
        if (idx < SEG) g_start[idx] += off;
    }
}

__global__ void fill_kernel(const float* __restrict__ e,
                            const int* __restrict__ ri_idx,
                            const int* __restrict__ ro_idx) {
    int t = blockIdx.x * blockDim.x + threadIdx.x;
    if (t >= BB * EE) return;
    int b = t / EE;
    float w = e[t];
    int ri = ri_idx[t];
    int ro = ro_idx[t];
    int s0 = (2 * b + 0) * NN + ri;
    int s1 = (2 * b + 1) * NN + ro;
    int p0 = g_start[s0] + atomicAdd(&g_fill[s0], 1);
    g_entry_src[p0] = ro;   // mi pulls X[ro]
    g_entry_w[p0]   = w;
    int p1 = g_start[s1] + atomicAdd(&g_fill[s1], 1);
    g_entry_src[p1] = ri;   // mo pulls X[ri]
    g_entry_w[p1]   = w;
}

// ---------------------------------------------------------------------------
// Gather: one warp per segment (b, dir, node). No atomics, no pre-zeroing.
// ---------------------------------------------------------------------------
__global__ void __launch_bounds__(256) gather_kernel(const float* __restrict__ X) {
    int task = blockIdx.x * (blockDim.x >> 5) + (threadIdx.x >> 5);
    if (task >= SEG) return;
    int lane = threadIdx.x & 31;

    int arr = task / NN;          // 0..3
    int n   = task - arr * NN;
    int b   = arr >> 1;
    int dir = arr & 1;

    int s   = g_start[task];
    int cnt = g_fill[task];

    const float4* Xb = reinterpret_cast<const float4*>(X + (size_t)b * NN * FF);

    float4 a0 = make_float4(0.f, 0.f, 0.f, 0.f);
    float4 a1 = a0;

    int i = s;
    int end = s + cnt;
    // unroll-by-2 for memory-level parallelism
    for (; i + 1 < end; i += 2) {
        float w0 = g_entry_w[i];     int s0 = g_entry_src[i];
        float w1 = g_entry_w[i + 1]; int s1 = g_entry_src[i + 1];
        const float4* r0p = Xb + (size_t)s0 * 64;
        const float4* r1p = Xb + (size_t)s1 * 64;
        float4 r00 = r0p[lane], r01 = r0p[lane + 32];
        float4 r10 = r1p[lane], r11 = r1p[lane + 32];
        a0.x = fmaf(w0, r00.x, a0.x); a0.y = fmaf(w0, r00.y, a0.y);
        a0.z = fmaf(w0, r00.z, a0.z); a0.w = fmaf(w0, r00.w, a0.w);
        a1.x = fmaf(w0, r01.x, a1.x); a1.y = fmaf(w0, r01.y, a1.y);
        a1.z = fmaf(w0, r01.z, a1.z); a1.w = fmaf(w0, r01.w, a1.w);
        a0.x = fmaf(w1, r10.x, a0.x); a0.y = fmaf(w1, r10.y, a0.y);
        a0.z = fmaf(w1, r10.z, a0.z); a0.w = fmaf(w1, r10.w, a0.w);
        a1.x = fmaf(w1, r11.x, a1.x); a1.y = fmaf(w1, r11.y, a1.y);
        a1.z = fmaf(w1, r11.z, a1.z); a1.w = fmaf(w1, r11.w, a1.w);
    }
    if (i < end) {
        float w = g_entry_w[i]; int sr = g_entry_src[i];
        const float4* rp = Xb + (size_t)sr * 64;
        float4 r0 = rp[lane], r1 = rp[lane + 32];
        a0.x = fmaf(w, r0.x, a0.x); a0.y = fmaf(w, r0.y, a0.y);
        a0.z = fmaf(w, r0.z, a0.z); a0.w = fmaf(w, r0.w, a0.w);
        a1.x = fmaf(w, r1.x, a1.x); a1.y = fmaf(w, r1.y, a1.y);
        a1.z = fmaf(w, r1.z, a1.z); a1.w = fmaf(w, r1.w, a1.w);
    }

    float4* dst = reinterpret_cast<float4*>(
        g_agg + ((size_t)b * NN + n) * 512 + dir * 256);
    dst[lane]      = a0;
    dst[lane + 32] = a1;
}

// ---------------------------------------------------------------------------
// Tiled fp32 GEMM + bias + tanh (unchanged from R1).
// ---------------------------------------------------------------------------
#define BM 64
#define BN 64
#define BK 16

__global__ void __launch_bounds__(256) mlp_gemm_kernel(
    const float* __restrict__ A0, int lda0, int ka0,
    const float* __restrict__ A1, int lda1,
    const float* __restrict__ W,
    const float* __restrict__ bias,
    float* __restrict__ Cout,
    int Ktot, int rows)
{
    __shared__ __align__(16) float As[BK][BM];
    __shared__ __align__(16) float Bs[BK][BN];

    const int tid = threadIdx.x;
    const int tx = tid & 15;
    const int ty = tid >> 4;
    const int rowBase = blockIdx.y * BM;
    const int colBase = blockIdx.x * BN;

    const int arow = tid >> 2;
    const int acol = (tid & 3) * 4;
    const int brow = tid >> 4;
    const int bcol = (tid & 15) * 4;

    float acc[4][4] = {};

    for (int k0 = 0; k0 < Ktot; k0 += BK) {
        float4 av;
        const int gr = rowBase + arow;
        if (gr < rows) {
            const float* ap;
            if (k0 < ka0) ap = A0 + (size_t)gr * lda0 + (k0 + acol);
            else          ap = A1 + (size_t)gr * lda1 + (k0 - ka0 + acol);
            av = *reinterpret_cast<const float4*>(ap);
        } else {
            av = make_float4(0.f, 0.f, 0.f, 0.f);
        }
        const float4 bv = *reinterpret_cast<const float4*>(
            W + (size_t)(k0 + brow) * 256 + colBase + bcol);

        __syncthreads();
        As[acol + 0][arow] = av.x;
        As[acol + 1][arow] = av.y;
        As[acol + 2][arow] = av.z;
        As[acol + 3][arow] = av.w;
        *reinterpret_cast<float4*>(&Bs[brow][bcol]) = bv;
        __syncthreads();

        #pragma unroll
        for (int k = 0; k < BK; k++) {
            float a[4], b[4];
            *reinterpret_cast<float4*>(a) = *reinterpret_cast<const float4*>(&As[k][ty * 4]);
            *reinterpret_cast<float4*>(b) = *reinterpret_cast<const float4*>(&Bs[k][tx * 4]);
            #pragma unroll
            for (int i = 0; i < 4; i++)
                #pragma unroll
                for (int j = 0; j < 4; j++)
                    acc[i][j] = fmaf(a[i], b[j], acc[i][j]);
        }
    }

    #pragma unroll
    for (int i = 0; i < 4; i++) {
        const int gr = rowBase + ty * 4 + i;
        if (gr < rows) {
            #pragma unroll
            for (int j = 0; j < 4; j++) {
                const int gc = colBase + tx * 4 + j;
                Cout[(size_t)gr * 256 + gc] = tanhf(acc[i][j] + bias[gc]);
            }
        }
    }
}

// ---------------------------------------------------------------------------
// Launcher. Inputs (metadata order): X, e, ri_idx, ro_idx, W1, b1, W2, b2
// ---------------------------------------------------------------------------
extern "C" void kernel_launch(void* const* d_in, const int* in_sizes, int n_in,
                              void* d_out, int out_size)
{
    (void)in_sizes; (void)n_in; (void)out_size;

    const float* X  = (const float*)d_in[0];
    const float* e  = (const float*)d_in[1];
    const int*   ri = (const int*)  d_in[2];
    const int*   ro = (const int*)  d_in[3];
    const float* W1 = (const float*)d_in[4];
    const float* b1 = (const float*)d_in[5];
    const float* W2 = (const float*)d_in[6];
    const float* b2 = (const float*)d_in[7];
    float* out = (float*)d_out;

    float* agg_ptr = nullptr;
    float* h_ptr   = nullptr;
    cudaGetSymbolAddress((void**)&agg_ptr, g_agg);
    cudaGetSymbolAddress((void**)&h_ptr,   g_h);

    // --- CSR build ---
    zero_counts_kernel<<<(SEG + 255) / 256, 256>>>();
    count_kernel<<<(BB * EE + 255) / 256, 256>>>(ri, ro);
    scan1_kernel<<<SCAN_NB, 256>>>();
    scan2_kernel<<<1, 128>>>();
    scan3_kernel<<<SCAN_NB, 256>>>();
    fill_kernel<<<(BB * EE + 255) / 256, 256>>>(e, ri, ro);

    // --- gather aggregation (writes all of g_agg, no atomics) ---
    gather_kernel<<<SEG / 8, 256>>>(X);

    // --- GEMM1: h = tanh([mi|mo|X] @ W1 + b1), K = 768 ---
    {
        dim3 grid(256 / BN, (RR + BM - 1) / BM);
        mlp_gemm_kernel<<<grid, 256>>>(agg_ptr, 512, 512, X, 256,
                                       W1, b1, h_ptr, KTOT, RR);
    }

    // --- GEMM2: out = tanh(h @ W2 + b2), K = 256 ---
    {
        dim3 grid(256 / BN, (RR + BM - 1) / BM);
        mlp_gemm_kernel<<<grid, 256>>>(h_ptr, 256, 256, nullptr, 0,
                                       W2, b2, out, 256, RR);
    }
}

// round 3
// speedup vs baseline: 1.9625x; 1.8961x over previous
#include <cuda_runtime.h>
#include <cstdint>
#include <cstddef>

// Problem constants (fixed by the reference)
#define BB   2
#define NN   50000
#define EE   150000
#define FF   256
#define OUTD 256
#define RR   (BB * NN)       // 100000 rows
#define KTOT (3 * FF)        // 768
#define SEG  (4 * NN)        // 200000 segments: (b,dir) x node
#define TOTE (4 * EE)        // 600000 CSR entries

// Scratch
__device__ float g_agg[(size_t)RR * 512];   // [r][0:256]=mi, [r][256:512]=mo
__device__ float g_h[(size_t)RR * OUTD];    // hidden activations

// CSR scratch
__device__ int   g_count[SEG];
__device__ int   g_fill[SEG];
__device__ int   g_start[SEG];
__device__ int   g_bsum[128];
__device__ int   g_entry_src[TOTE];
__device__ float g_entry_w[TOTE];

#define SCAN_TILE 2048
#define SCAN_NB   ((SEG + SCAN_TILE - 1) / SCAN_TILE)   // 98

// ---------------------------------------------------------------------------
// CSR build (unchanged from R2 — measured cheap)
// ---------------------------------------------------------------------------
__global__ void zero_counts_kernel() {
    int i = blockIdx.x * blockDim.x + threadIdx.x;
    if (i < SEG) { g_count[i] = 0; g_fill[i] = 0; }
}

__global__ void count_kernel(const int* __restrict__ ri_idx,
                             const int* __restrict__ ro_idx) {
    int t = blockIdx.x * blockDim.x + threadIdx.x;
    if (t >= BB * EE) return;
    int b = t / EE;
    atomicAdd(&g_count[(2 * b + 0) * NN + ri_idx[t]], 1);
    atomicAdd(&g_count[(2 * b + 1) * NN + ro_idx[t]], 1);
}

__global__ void __launch_bounds__(256) scan1_kernel() {
    __shared__ int sh[256];
    const int base = blockIdx.x * SCAN_TILE + threadIdx.x * 8;
    int v[8]; int s = 0;
    #pragma unroll
    for (int j = 0; j < 8; j++) {
        int idx = base + j;
        int x = (idx < SEG) ? g_count[idx] : 0;
        v[j] = s;
        s += x;
    }
    sh[threadIdx.x] = s;
    __syncthreads();
    int acc = s;
    #pragma unroll
    for (int off = 1; off < 256; off <<= 1) {
        int t = (threadIdx.x >= off) ? sh[threadIdx.x - off] : 0;
        __syncthreads();
        acc += t;
        sh[threadIdx.x] = acc;
        __syncthreads();
    }
    int excl = acc - s;
    #pragma unroll
    for (int j = 0; j < 8; j++) {
        int idx = base + j;
        if (idx < SEG) g_start[idx] = excl + v[j];
    }
    if (threadIdx.x == 255) g_bsum[blockIdx.x] = acc;
}

__global__ void scan2_kernel() {
    __shared__ int sh[128];
    int t = threadIdx.x;
    int x = (t < SCAN_NB) ? g_bsum[t] : 0;
    sh[t] = x;
    __syncthreads();
    int acc = x;
    #pragma unroll
    for (int off = 1; off < 128; off <<= 1) {
        int y = (t >= off) ? sh[t - off] : 0;
        __syncthreads();
        acc += y;
        sh[t] = acc;
        __syncthreads();
    }
    if (t < SCAN_NB) g_bsum[t] = acc - x;
}

__global__ void __launch_bounds__(256) scan3_kernel() {
    int off = g_bsum[blockIdx.x];
    int base = blockIdx.x * SCAN_TILE + threadIdx.x * 8;
    #pragma unroll
    for (int j = 0; j < 8; j++) {
        int idx = base + j;
        if (idx < SEG) g_start[idx] += off;
    }
}

__global__ void fill_kernel(const float* __restrict__ e,
                            const int* __restrict__ ri_idx,
                            const int* __restrict__ ro_idx) {
    int t = blockIdx.x * blockDim.x + threadIdx.x;
    if (t >= BB * EE) return;
    int b = t / EE;
    float w = e[t];
    int ri = ri_idx[t];
    int ro = ro_idx[t];
    int s0 = (2 * b + 0) * NN + ri;
    int s1 = (2 * b + 1) * NN + ro;
    int p0 = g_start[s0] + atomicAdd(&g_fill[s0], 1);
    g_entry_src[p0] = ro;
    g_entry_w[p0]   = w;
    int p1 = g_start[s1] + atomicAdd(&g_fill[s1], 1);
    g_entry_src[p1] = ri;
    g_entry_w[p1]   = w;
}

// ---------------------------------------------------------------------------
// Gather: one warp per segment (b, dir, node). No atomics, no pre-zeroing.
// ---------------------------------------------------------------------------
__global__ void __launch_bounds__(256) gather_kernel(const float* __restrict__ X) {
    int task = blockIdx.x * (blockDim.x >> 5) + (threadIdx.x >> 5);
    if (task >= SEG) return;
    int lane = threadIdx.x & 31;

    int arr = task / NN;
    int n   = task - arr * NN;
    int b   = arr >> 1;
    int dir = arr & 1;

    int s   = g_start[task];
    int cnt = g_fill[task];

    const float4* Xb = reinterpret_cast<const float4*>(X + (size_t)b * NN * FF);

    float4 a0 = make_float4(0.f, 0.f, 0.f, 0.f);
    float4 a1 = a0;

    int i = s, end = s + cnt;
    for (; i + 1 < end; i += 2) {
        float w0 = g_entry_w[i];     int s0 = g_entry_src[i];
        float w1 = g_entry_w[i + 1]; int s1 = g_entry_src[i + 1];
        const float4* r0p = Xb + (size_t)s0 * 64;
        const float4* r1p = Xb + (size_t)s1 * 64;
        float4 r00 = r0p[lane], r01 = r0p[lane + 32];
        float4 r10 = r1p[lane], r11 = r1p[lane + 32];
        a0.x = fmaf(w0, r00.x, a0.x); a0.y = fmaf(w0, r00.y, a0.y);
        a0.z = fmaf(w0, r00.z, a0.z); a0.w = fmaf(w0, r00.w, a0.w);
        a1.x = fmaf(w0, r01.x, a1.x); a1.y = fmaf(w0, r01.y, a1.y);
        a1.z = fmaf(w0, r01.z, a1.z); a1.w = fmaf(w0, r01.w, a1.w);
        a0.x = fmaf(w1, r10.x, a0.x); a0.y = fmaf(w1, r10.y, a0.y);
        a0.z = fmaf(w1, r10.z, a0.z); a0.w = fmaf(w1, r10.w, a0.w);
        a1.x = fmaf(w1, r11.x, a1.x); a1.y = fmaf(w1, r11.y, a1.y);
        a1.z = fmaf(w1, r11.z, a1.z); a1.w = fmaf(w1, r11.w, a1.w);
    }
    if (i < end) {
        float w = g_entry_w[i]; int sr = g_entry_src[i];
        const float4* rp = Xb + (size_t)sr * 64;
        float4 r0 = rp[lane], r1 = rp[lane + 32];
        a0.x = fmaf(w, r0.x, a0.x); a0.y = fmaf(w, r0.y, a0.y);
        a0.z = fmaf(w, r0.z, a0.z); a0.w = fmaf(w, r0.w, a0.w);
        a1.x = fmaf(w, r1.x, a1.x); a1.y = fmaf(w, r1.y, a1.y);
        a1.z = fmaf(w, r1.z, a1.z); a1.w = fmaf(w, r1.w, a1.w);
    }

    float4* dst = reinterpret_cast<float4*>(
        g_agg + ((size_t)b * NN + n) * 512 + dir * 256);
    dst[lane]      = a0;
    dst[lane + 32] = a1;
}

// ---------------------------------------------------------------------------
// Tensor-core GEMM (tf32 mma.sync) + bias + tanh.approx
//   C[rows x 256] = tanh( A[rows x Ktot] @ W[Ktot x 256] + bias )
// Block tile 128(M) x 256(N, full width => A read exactly once) x 16(K).
// 512 threads = 16 warps in 4(M) x 4(N); warp tile 32x64; mma m16n8k8.
// ---------------------------------------------------------------------------
#define GBM 128
#define GBK 16
#define APAD 4     // As[m][GBK+APAD]: fragment loads hit 32 distinct banks
#define BPAD 4     // Bs[n][GBK+BPAD]

__device__ __forceinline__ float to_tf32(float x) {
    uint32_t u;
    asm("cvt.rna.tf32.f32 %0, %1;" : "=r"(u) : "f"(x));
    return __uint_as_float(u);
}

__device__ __forceinline__ float tanh_approx(float x) {
    float y;
    asm("tanh.approx.f32 %0, %1;" : "=f"(y) : "f"(x));
    return y;
}

__device__ __forceinline__ void mma_tf32(float c[4],
                                         uint32_t a0, uint32_t a1, uint32_t a2, uint32_t a3,
                                         uint32_t b0, uint32_t b1) {
    asm volatile(
        "mma.sync.aligned.m16n8k8.row.col.f32.tf32.tf32.f32 "
        "{%0,%1,%2,%3}, {%4,%5,%6,%7}, {%8,%9}, {%0,%1,%2,%3};"
        : "+f"(c[0]), "+f"(c[1]), "+f"(c[2]), "+f"(c[3])
        : "r"(a0), "r"(a1), "r"(a2), "r"(a3), "r"(b0), "r"(b1));
}

__global__ void __launch_bounds__(512, 1) mma_gemm_kernel(
    const float* __restrict__ A0, int lda0, int ka0,
    const float* __restrict__ A1, int lda1,
    const float* __restrict__ W,
    const float* __restrict__ bias,
    float* __restrict__ Cout,
    int Ktot, int rows)
{
    __shared__ float As[GBM][GBK + APAD];   // [m][k], tf32 bits
    __shared__ float Bs[256][GBK + BPAD];   // W transposed: [n][k], tf32 bits

    const int tid  = threadIdx.x;
    const int warp = tid >> 5;
    const int lane = tid & 31;
    const int g    = lane >> 2;       // group id 0..7
    const int tg   = lane & 3;        // thread-in-group 0..3
    const int wm   = warp & 3;        // warp M index 0..3 (32 rows each)
    const int wn   = warp >> 2;       // warp N index 0..3 (64 cols each)
    const int rowBase = blockIdx.x * GBM;

    // A staging map: thread -> (row 0..127, k-group of 4)
    const int arow = tid >> 2;
    const int akc  = (tid & 3) * 4;
    // W staging map: thread -> (k 0..15, n-col4 0..31) x 2 halves
    const int wk  = tid & 15;
    const int wc4 = tid >> 4;          // 0..31

    float acc[2][8][4];
    #pragma unroll
    for (int mt = 0; mt < 2; mt++)
        #pragma unroll
        for (int nt = 0; nt < 8; nt++)
            #pragma unroll
            for (int r = 0; r < 4; r++) acc[mt][nt][r] = 0.f;

    for (int k0 = 0; k0 < Ktot; k0 += GBK) {
        // ---- global loads ----
        float4 av = make_float4(0.f, 0.f, 0.f, 0.f);
        {
            const int gr = rowBase + arow;
            if (gr < rows) {
                const float* ap;
                if (k0 < ka0) ap = A0 + (size_t)gr * lda0 + (k0 + akc);
                else          ap = A1 + (size_t)gr * lda1 + (k0 - ka0 + akc);
                av = *reinterpret_cast<const float4*>(ap);
            }
        }
        float4 wv0 = *reinterpret_cast<const float4*>(
            W + (size_t)(k0 + wk) * 256 + wc4 * 4);
        float4 wv1 = *reinterpret_cast<const float4*>(
            W + (size_t)(k0 + wk) * 256 + (wc4 + 32) * 4);

        __syncthreads();   // previous iteration smem reads done

        // ---- smem stores (tf32-converted) ----
        As[arow][akc + 0] = to_tf32(av.x);
        As[arow][akc + 1] = to_tf32(av.y);
        As[arow][akc + 2] = to_tf32(av.z);
        As[arow][akc + 3] = to_tf32(av.w);

        {
            int n0 = wc4 * 4;
            Bs[n0 + 0][wk] = to_tf32(wv0.x);
            Bs[n0 + 1][wk] = to_tf32(wv0.y);
            Bs[n0 + 2][wk] = to_tf32(wv0.z);
            Bs[n0 + 3][wk] = to_tf32(wv0.w);
            int n1 = (wc4 + 32) * 4;
            Bs[n1 + 0][wk] = to_tf32(wv1.x);
            Bs[n1 + 1][wk] = to_tf32(wv1.y);
            Bs[n1 + 2][wk] = to_tf32(wv1.z);
            Bs[n1 + 3][wk] = to_tf32(wv1.w);
        }
        __syncthreads();

        // ---- two k8 sub-steps of mma ----
        #pragma unroll
        for (int ks = 0; ks < 2; ks++) {
            const int kb = ks * 8;
            uint32_t a[2][4];
            #pragma unroll
            for (int mt = 0; mt < 2; mt++) {
                const int r = wm * 32 + mt * 16 + g;
                a[mt][0] = __float_as_uint(As[r    ][kb + tg    ]);
                a[mt][1] = __float_as_uint(As[r + 8][kb + tg    ]);
                a[mt][2] = __float_as_uint(As[r    ][kb + tg + 4]);
                a[mt][3] = __float_as_uint(As[r + 8][kb + tg + 4]);
            }
            uint32_t b[8][2];
            #pragma unroll
            for (int nt = 0; nt < 8; nt++) {
                const int n = wn * 64 + nt * 8 + g;
                b[nt][0] = __float_as_uint(Bs[n][kb + tg    ]);
                b[nt][1] = __float_as_uint(Bs[n][kb + tg + 4]);
            }
            #pragma unroll
            for (int mt = 0; mt < 2; mt++)
                #pragma unroll
                for (int nt = 0; nt < 8; nt++)
                    mma_tf32(acc[mt][nt], a[mt][0], a[mt][1], a[mt][2], a[mt][3],
                             b[nt][0], b[nt][1]);
        }
    }

    // ---- epilogue: bias + tanh, float2 stores ----
    #pragma unroll
    for (int mt = 0; mt < 2; mt++) {
        const int r0 = rowBase + wm * 32 + mt * 16 + g;
        #pragma unroll
        for (int nt = 0; nt < 8; nt++) {
            const int col = wn * 64 + nt * 8 + tg * 2;
            const float b0 = bias[col];
            const float b1 = bias[col + 1];
            if (r0 < rows) {
                float2 v;
                v.x = tanh_approx(acc[mt][nt][0] + b0);
                v.y = tanh_approx(acc[mt][nt][1] + b1);
                *reinterpret_cast<float2*>(Cout + (size_t)r0 * 256 + col) = v;
            }
            if (r0 + 8 < rows) {
                float2 v;
                v.x = tanh_approx(acc[mt][nt][2] + b0);
                v.y = tanh_approx(acc[mt][nt][3] + b1);
                *reinterpret_cast<float2*>(Cout + (size_t)(r0 + 8) * 256 + col) = v;
            }
        }
    }
}

// ---------------------------------------------------------------------------
// Launcher. Inputs (metadata order): X, e, ri_idx, ro_idx, W1, b1, W2, b2
// ---------------------------------------------------------------------------
extern "C" void kernel_launch(void* const* d_in, const int* in_sizes, int n_in,
                              void* d_out, int out_size)
{
    (void)in_sizes; (void)n_in; (void)out_size;

    const float* X  = (const float*)d_in[0];
    const float* e  = (const float*)d_in[1];
    const int*   ri = (const int*)  d_in[2];
    const int*   ro = (const int*)  d_in[3];
    const float* W1 = (const float*)d_in[4];
    const float* b1 = (const float*)d_in[5];
    const float* W2 = (const float*)d_in[6];
    const float* b2 = (const float*)d_in[7];
    float* out = (float*)d_out;

    float* agg_ptr = nullptr;
    float* h_ptr   = nullptr;
    cudaGetSymbolAddress((void**)&agg_ptr, g_agg);
    cudaGetSymbolAddress((void**)&h_ptr,   g_h);

    // --- CSR build + gather aggregation ---
    zero_counts_kernel<<<(SEG + 255) / 256, 256>>>();
    count_kernel<<<(BB * EE + 255) / 256, 256>>>(ri, ro);
    scan1_kernel<<<SCAN_NB, 256>>>();
    scan2_kernel<<<1, 128>>>();
    scan3_kernel<<<SCAN_NB, 256>>>();
    fill_kernel<<<(BB * EE + 255) / 256, 256>>>(e, ri, ro);
    gather_kernel<<<SEG / 8, 256>>>(X);

    const int nblk = (RR + GBM - 1) / GBM;   // 782

    // --- GEMM1: h = tanh([mi|mo|X] @ W1 + b1), K = 768 ---
    mma_gemm_kernel<<<nblk, 512>>>(agg_ptr, 512, 512, X, 256,
                                   W1, b1, h_ptr, KTOT, RR);

    // --- GEMM2: out = tanh(h @ W2 + b2), K = 256 ---
    mma_gemm_kernel<<<nblk, 512>>>(h_ptr, 256, KTOT, nullptr, 0,
                                   W2, b2, out, 256, RR);
}

// round 4
// speedup vs baseline: 1.9822x; 1.0100x over previous
#include <cuda_runtime.h>
#include <cstdint>
#include <cstddef>

// Problem constants (fixed by the reference)
#define BB   2
#define NN   50000
#define EE   150000
#define FF   256
#define OUTD 256
#define RR   (BB * NN)       // 100000 rows
#define KTOT (3 * FF)        // 768
#define SEG  (4 * NN)        // 200000 segments: (b,dir) x node
#define TOTE (4 * EE)        // 600000 CSR entries

// Scratch
__device__ float g_agg[(size_t)RR * 512];   // [r][0:256]=mi, [r][256:512]=mo
__device__ float g_h[(size_t)RR * OUTD];    // hidden activations

// CSR scratch (self-cleaning across calls; BSS zero-init on first call)
__device__ int   g_count[SEG];
__device__ int   g_fill[SEG];
__device__ int   g_start[SEG];
__device__ int   g_entry_src[TOTE];
__device__ float g_entry_w[TOTE];

#define SCAN_TILE 2048
#define SCAN_NB   ((SEG + SCAN_TILE - 1) / SCAN_TILE)   // 98

// decoupled-lookback state
__device__ volatile int g_scan_state[SCAN_NB];  // 0=none, 1=agg ready, 2=incl ready
__device__ int g_scan_agg[SCAN_NB];
__device__ int g_scan_incl[SCAN_NB];

// ---------------------------------------------------------------------------
// 1) count: histogram segment sizes (g_count pre-zeroed by previous call's scan)
// ---------------------------------------------------------------------------
__global__ void count_kernel(const int* __restrict__ ri_idx,
                             const int* __restrict__ ro_idx) {
    int t = blockIdx.x * blockDim.x + threadIdx.x;
    if (t >= BB * EE) return;
    int b = t / EE;
    atomicAdd(&g_count[(2 * b + 0) * NN + ri_idx[t]], 1);
    atomicAdd(&g_count[(2 * b + 1) * NN + ro_idx[t]], 1);
}

// ---------------------------------------------------------------------------
// 2) scan: single-pass decoupled lookback; also re-zeros g_count for next call
//    98 blocks <= 148 SMs -> all resident, spin-wait is safe.
// ---------------------------------------------------------------------------
__global__ void __launch_bounds__(256) scan_kernel() {
    __shared__ int sh[256];
    __shared__ int s_off;
    const int bid = blockIdx.x;
    const int base = bid * SCAN_TILE + threadIdx.x * 8;

    int v[8]; int s = 0;
    #pragma unroll
    for (int j = 0; j < 8; j++) {
        int idx = base + j;
        int x = 0;
        if (idx < SEG) { x = g_count[idx]; g_count[idx] = 0; }
        v[j] = s;
        s += x;
    }
    sh[threadIdx.x] = s;
    __syncthreads();
    int acc = s;
    #pragma unroll
    for (int off = 1; off < 256; off <<= 1) {
        int t = (threadIdx.x >= off) ? sh[threadIdx.x - off] : 0;
        __syncthreads();
        acc += t;
        sh[threadIdx.x] = acc;
        __syncthreads();
    }
    const int excl_thread = acc - s;   // exclusive prefix within block

    // publish aggregate (thread 255 holds the block total in acc)
    if (threadIdx.x == 255) {
        if (bid == 0) {
            g_scan_incl[0] = acc;
            __threadfence();
            g_scan_state[0] = 2;
            s_off = 0;
        } else {
            g_scan_agg[bid] = acc;
            __threadfence();
            g_scan_state[bid] = 1;
        }
    }
    // lookback
    if (bid > 0 && threadIdx.x == 0) {
        int off = 0;
        int j = bid - 1;
        while (true) {
            int st;
            do { st = g_scan_state[j]; } while (st == 0);
            __threadfence();
            if (st == 2) { off += g_scan_incl[j]; break; }
            off += g_scan_agg[j];
            j--;
        }
        s_off = off;
    }
    __syncthreads();
    const int off = s_off;
    if (bid > 0 && threadIdx.x == 255) {
        g_scan_incl[bid] = off + acc;
        __threadfence();
        g_scan_state[bid] = 2;
    }
    #pragma unroll
    for (int j = 0; j < 8; j++) {
        int idx = base + j;
        if (idx < SEG) g_start[idx] = off + excl_thread + v[j];
    }
}

// ---------------------------------------------------------------------------
// 3) fill CSR entries; also resets scan flags for next call
// ---------------------------------------------------------------------------
__global__ void fill_kernel(const float* __restrict__ e,
                            const int* __restrict__ ri_idx,
                            const int* __restrict__ ro_idx) {
    int t = blockIdx.x * blockDim.x + threadIdx.x;
    if (t < SCAN_NB) g_scan_state[t] = 0;     // cleanup for next call
    if (t >= BB * EE) return;
    int b = t / EE;
    float w = e[t];
    int ri = ri_idx[t];
    int ro = ro_idx[t];
    int s0 = (2 * b + 0) * NN + ri;
    int s1 = (2 * b + 1) * NN + ro;
    int p0 = g_start[s0] + atomicAdd(&g_fill[s0], 1);
    g_entry_src[p0] = ro;
    g_entry_w[p0]   = w;
    int p1 = g_start[s1] + atomicAdd(&g_fill[s1], 1);
    g_entry_src[p1] = ri;
    g_entry_w[p1]   = w;
}

// ---------------------------------------------------------------------------
// 4) gather: one warp per segment; no atomics; resets g_fill for next call
// ---------------------------------------------------------------------------
__global__ void __launch_bounds__(256) gather_kernel(const float* __restrict__ X) {
    int task = blockIdx.x * (blockDim.x >> 5) + (threadIdx.x >> 5);
    if (task >= SEG) return;
    int lane = threadIdx.x & 31;

    int arr = task / NN;
    int n   = task - arr * NN;
    int b   = arr >> 1;
    int dir = arr & 1;

    int s = g_start[task];
    int cnt;
    if (lane == 0) { cnt = g_fill[task]; g_fill[task] = 0; }
    cnt = __shfl_sync(0xffffffffu, cnt, 0);

    const float4* Xb = reinterpret_cast<const float4*>(X + (size_t)b * NN * FF);

    float4 a0 = make_float4(0.f, 0.f, 0.f, 0.f);
    float4 a1 = a0;

    int i = s, end = s + cnt;
    for (; i + 1 < end; i += 2) {
        float w0 = g_entry_w[i];     int s0 = g_entry_src[i];
        float w1 = g_entry_w[i + 1]; int s1 = g_entry_src[i + 1];
        const float4* r0p = Xb + (size_t)s0 * 64;
        const float4* r1p = Xb + (size_t)s1 * 64;
        float4 r00 = r0p[lane], r01 = r0p[lane + 32];
        float4 r10 = r1p[lane], r11 = r1p[lane + 32];
        a0.x = fmaf(w0, r00.x, a0.x); a0.y = fmaf(w0, r00.y, a0.y);
        a0.z = fmaf(w0, r00.z, a0.z); a0.w = fmaf(w0, r00.w, a0.w);
        a1.x = fmaf(w0, r01.x, a1.x); a1.y = fmaf(w0, r01.y, a1.y);
        a1.z = fmaf(w0, r01.z, a1.z); a1.w = fmaf(w0, r01.w, a1.w);
        a0.x = fmaf(w1, r10.x, a0.x); a0.y = fmaf(w1, r10.y, a0.y);
        a0.z = fmaf(w1, r10.z, a0.z); a0.w = fmaf(w1, r10.w, a0.w);
        a1.x = fmaf(w1, r11.x, a1.x); a1.y = fmaf(w1, r11.y, a1.y);
        a1.z = fmaf(w1, r11.z, a1.z); a1.w = fmaf(w1, r11.w, a1.w);
    }
    if (i < end) {
        float w = g_entry_w[i]; int sr = g_entry_src[i];
        const float4* rp = Xb + (size_t)sr * 64;
        float4 r0 = rp[lane], r1 = rp[lane + 32];
        a0.x = fmaf(w, r0.x, a0.x); a0.y = fmaf(w, r0.y, a0.y);
        a0.z = fmaf(w, r0.z, a0.z); a0.w = fmaf(w, r0.w, a0.w);
        a1.x = fmaf(w, r1.x, a1.x); a1.y = fmaf(w, r1.y, a1.y);
        a1.z = fmaf(w, r1.z, a1.z); a1.w = fmaf(w, r1.w, a1.w);
    }

    float4* dst = reinterpret_cast<float4*>(
        g_agg + ((size_t)b * NN + n) * 512 + dir * 256);
    dst[lane]      = a0;
    dst[lane + 32] = a1;
}

// ---------------------------------------------------------------------------
// 5/6) Tensor-core GEMM, 4-stage cp.async pipeline + bias + tanh.approx
//   C[rows x 256] = tanh( A[rows x Ktot] @ W[Ktot x 256] + bias )
// Block 128(M) x 256(N, full width) x 16(K); 512 threads = 4x4 warps,
// warp tile 32x64, mma m16n8k8 tf32 (cvt.rna at fragment load).
// smem layouts: As[st][128][20] (banks 20g+tg all-distinct),
//               Bs[st][16][264] (banks 8tg+g all-distinct).
// ---------------------------------------------------------------------------
#define GBM 128
#define GBK 16
#define NSTAGE 4
#define A_LD 20
#define B_LD 264
#define A_STG (GBM * A_LD)          // floats per A stage = 2560
#define B_STG (GBK * B_LD)          // floats per B stage = 4224
#define SMEM_FLOATS (NSTAGE * (A_STG + B_STG))   // 27136 floats = 108544 B

__device__ __forceinline__ uint32_t f2tf(float x) {
    uint32_t u;
    asm("cvt.rna.tf32.f32 %0, %1;" : "=r"(u) : "f"(x));
    return u;
}

__device__ __forceinline__ float tanh_approx(float x) {
    float y;
    asm("tanh.approx.f32 %0, %1;" : "=f"(y) : "f"(x));
    return y;
}

__device__ __forceinline__ void mma_tf32(float c[4],
                                         uint32_t a0, uint32_t a1, uint32_t a2, uint32_t a3,
                                         uint32_t b0, uint32_t b1) {
    asm volatile(
        "mma.sync.aligned.m16n8k8.row.col.f32.tf32.tf32.f32 "
        "{%0,%1,%2,%3}, {%4,%5,%6,%7}, {%8,%9}, {%0,%1,%2,%3};"
        : "+f"(c[0]), "+f"(c[1]), "+f"(c[2]), "+f"(c[3])
        : "r"(a0), "r"(a1), "r"(a2), "r"(a3), "r"(b0), "r"(b1));
}

__device__ __forceinline__ void cp16(uint32_t dst_smem, const void* src, int src_bytes) {
    asm volatile("cp.async.cg.shared.global [%0], [%1], 16, %2;"
                 :: "r"(dst_smem), "l"(src), "r"(src_bytes));
}

__global__ void __launch_bounds__(512, 1) mma_gemm_kernel(
    const float* __restrict__ A0, int lda0, int ka0,
    const float* __restrict__ A1, int lda1,
    const float* __restrict__ W,
    const float* __restrict__ bias,
    float* __restrict__ Cout,
    int Ktot, int rows)
{
    extern __shared__ float smem[];
    float* AsB = smem;                       // NSTAGE * A_STG
    float* BsB = smem + NSTAGE * A_STG;      // NSTAGE * B_STG
    const uint32_t smem_u32 = (uint32_t)__cvta_generic_to_shared(smem);
    const uint32_t As_u32 = smem_u32;
    const uint32_t Bs_u32 = smem_u32 + NSTAGE * A_STG * 4;

    const int tid  = threadIdx.x;
    const int warp = tid >> 5;
    const int lane = tid & 31;
    const int g    = lane >> 2;
    const int tg   = lane & 3;
    const int wm   = warp & 3;
    const int wn   = warp >> 2;
    const int rowBase = blockIdx.x * GBM;

    // stage-load maps
    const int arow = tid >> 2;            // 0..127
    const int akc  = (tid & 3) * 4;       // 0,4,8,12
    const int wk   = tid & 15;            // 0..15
    const int wc4  = tid >> 4;            // 0..31

    const int gr = rowBase + arow;
    const bool avalid = (gr < rows);
    const int abytes = avalid ? 16 : 0;

    const int ntiles = Ktot / GBK;

    float acc[2][8][4];
    #pragma unroll
    for (int mt = 0; mt < 2; mt++)
        #pragma unroll
        for (int nt = 0; nt < 8; nt++)
            #pragma unroll
            for (int r = 0; r < 4; r++) acc[mt][nt][r] = 0.f;

    // ---- tile loader ----
    auto load_tile = [&](int st, int t) {
        const int k0 = t * GBK;
        const float* asrc;
        if (k0 < ka0) asrc = A0 + (size_t)gr * lda0 + (k0 + akc);
        else          asrc = A1 + (size_t)gr * lda1 + (k0 - ka0 + akc);
        cp16(As_u32 + (uint32_t)((st * A_STG + arow * A_LD + akc) * 4), asrc, abytes);

        const float* wsrc = W + (size_t)(k0 + wk) * 256 + wc4 * 4;
        cp16(Bs_u32 + (uint32_t)((st * B_STG + wk * B_LD + wc4 * 4) * 4), wsrc, 16);
        cp16(Bs_u32 + (uint32_t)((st * B_STG + wk * B_LD + (wc4 + 32) * 4) * 4), wsrc + 128, 16);
    };

    // ---- prologue: prefetch NSTAGE-1 tiles ----
    #pragma unroll
    for (int t = 0; t < NSTAGE - 1; t++) {
        if (t < ntiles) load_tile(t, t);
        asm volatile("cp.async.commit_group;");
    }

    for (int t = 0; t < ntiles; t++) {
        asm volatile("cp.async.wait_group %0;" :: "n"(NSTAGE - 2));
        __syncthreads();

        const int st = t & (NSTAGE - 1);
        // prefetch tile t+3 into the stage freed by tile t-1
        {
            const int tn = t + NSTAGE - 1;
            if (tn < ntiles) load_tile(tn & (NSTAGE - 1), tn);
            asm volatile("cp.async.commit_group;");
        }

        const float* Ast = AsB + st * A_STG;
        const float* Bst = BsB + st * B_STG;

        #pragma unroll
        for (int ks = 0; ks < 2; ks++) {
            const int kb = ks * 8;
            uint32_t a[2][4];
            #pragma unroll
            for (int mt = 0; mt < 2; mt++) {
                const int r = wm * 32 + mt * 16 + g;
                a[mt][0] = f2tf(Ast[(r    ) * A_LD + kb + tg    ]);
                a[mt][1] = f2tf(Ast[(r + 8) * A_LD + kb + tg    ]);
                a[mt][2] = f2tf(Ast[(r    ) * A_LD + kb + tg + 4]);
                a[mt][3] = f2tf(Ast[(r + 8) * A_LD + kb + tg + 4]);
            }
            uint32_t b[8][2];
            #pragma unroll
            for (int nt = 0; nt < 8; nt++) {
                const int n = wn * 64 + nt * 8 + g;
                b[nt][0] = f2tf(Bst[(kb + tg    ) * B_LD + n]);
                b[nt][1] = f2tf(Bst[(kb + tg + 4) * B_LD + n]);
            }
            #pragma unroll
            for (int mt = 0; mt < 2; mt++)
                #pragma unroll
                for (int nt = 0; nt < 8; nt++)
                    mma_tf32(acc[mt][nt], a[mt][0], a[mt][1], a[mt][2], a[mt][3],
                             b[nt][0], b[nt][1]);
        }
    }

    // ---- epilogue: bias + tanh, float2 stores ----
    #pragma unroll
    for (int mt = 0; mt < 2; mt++) {
        const int r0 = rowBase + wm * 32 + mt * 16 + g;
        #pragma unroll
        for (int nt = 0; nt < 8; nt++) {
            const int col = wn * 64 + nt * 8 + tg * 2;
            const float b0 = bias[col];
            const float b1 = bias[col + 1];
            if (r0 < rows) {
                float2 v;
                v.x = tanh_approx(acc[mt][nt][0] + b0);
                v.y = tanh_approx(acc[mt][nt][1] + b1);
                *reinterpret_cast<float2*>(Cout + (size_t)r0 * 256 + col) = v;
            }
            if (r0 + 8 < rows) {
                float2 v;
                v.x = tanh_approx(acc[mt][nt][2] + b0);
                v.y = tanh_approx(acc[mt][nt][3] + b1);
                *reinterpret_cast<float2*>(Cout + (size_t)(r0 + 8) * 256 + col) = v;
            }
        }
    }
}

// ---------------------------------------------------------------------------
// Launcher. Inputs (metadata order): X, e, ri_idx, ro_idx, W1, b1, W2, b2
// ---------------------------------------------------------------------------
extern "C" void kernel_launch(void* const* d_in, const int* in_sizes, int n_in,
                              void* d_out, int out_size)
{
    (void)in_sizes; (void)n_in; (void)out_size;

    const float* X  = (const float*)d_in[0];
    const float* e  = (const float*)d_in[1];
    const int*   ri = (const int*)  d_in[2];
    const int*   ro = (const int*)  d_in[3];
    const float* W1 = (const float*)d_in[4];
    const float* b1 = (const float*)d_in[5];
    const float* W2 = (const float*)d_in[6];
    const float* b2 = (const float*)d_in[7];
    float* out = (float*)d_out;

    float* agg_ptr = nullptr;
    float* h_ptr   = nullptr;
    cudaGetSymbolAddress((void**)&agg_ptr, g_agg);
    cudaGetSymbolAddress((void**)&h_ptr,   g_h);

    const int smem_bytes = SMEM_FLOATS * 4;   // 108544
    cudaFuncSetAttribute(mma_gemm_kernel,
                         cudaFuncAttributeMaxDynamicSharedMemorySize, smem_bytes);

    // --- CSR build + gather aggregation (self-cleaning kernels) ---
    count_kernel<<<(BB * EE + 255) / 256, 256>>>(ri, ro);
    scan_kernel<<<SCAN_NB, 256>>>();
    fill_kernel<<<(BB * EE + 255) / 256, 256>>>(e, ri, ro);
    gather_kernel<<<SEG / 8, 256>>>(X);       // 4th launch -> profiled

    const int nblk = (RR + GBM - 1) / GBM;    // 782

    // --- GEMM1: h = tanh([mi|mo|X] @ W1 + b1), K = 768 ---
    mma_gemm_kernel<<<nblk, 512, smem_bytes>>>(agg_ptr, 512, 512, X, 256,
                                               W1, b1, h_ptr, KTOT, RR);

    // --- GEMM2: out = tanh(h @ W2 + b2), K = 256 ---
    mma_gemm_kernel<<<nblk, 512, smem_bytes>>>(h_ptr, 256, KTOT, nullptr, 0,
                                               W2, b2, out, 256, RR);
}

// round 6
// speedup vs baseline: 2.6815x; 1.3528x over previous
#include <cuda_runtime.h>
#include <cstdint>
#include <cstddef>

// Problem constants (fixed by the reference)
#define BB   2
#define NN   50000
#define EE   150000
#define FF   256
#define OUTD 256
#define RR   (BB * NN)       // 100000 rows
#define KTOT (3 * FF)        // 768
#define SEG  (4 * NN)        // 200000 segments
#define TOTE (4 * EE)        // 600000 CSR entries

// Scratch
__device__ float g_agg[(size_t)RR * 512];   // [r][0:256]=mi, [r][256:512]=mo
__device__ float g_h[(size_t)RR * OUTD];

// CSR scratch (self-cleaning across calls)
__device__ int   g_count[SEG];
__device__ int   g_fill[SEG];
__device__ int   g_start[SEG];
__device__ int   g_entry_src[TOTE];
__device__ float g_entry_w[TOTE];

#define SCAN_TILE 2048
#define SCAN_NB   ((SEG + SCAN_TILE - 1) / SCAN_TILE)   // 98
__device__ volatile int g_scan_state[SCAN_NB];
__device__ int g_scan_agg[SCAN_NB];
__device__ int g_scan_incl[SCAN_NB];

// ---------------------------------------------------------------------------
// helpers
// ---------------------------------------------------------------------------
__device__ __forceinline__ uint32_t f2tf(float x) {
    uint32_t u;
    asm("cvt.rna.tf32.f32 %0, %1;" : "=r"(u) : "f"(x));
    return u;
}
__device__ __forceinline__ float tf32r(float x) { return __uint_as_float(f2tf(x)); }
__device__ __forceinline__ float tanh_approx(float x) {
    float y;
    asm("tanh.approx.f32 %0, %1;" : "=f"(y) : "f"(x));
    return y;
}
__device__ __forceinline__ void cp16(uint32_t dst, const void* src, int bytes) {
    asm volatile("cp.async.cg.shared.global [%0], [%1], 16, %2;"
                 :: "r"(dst), "l"(src), "r"(bytes));
}
__device__ __forceinline__ void mma_tf32(float c[4],
                                         uint32_t a0, uint32_t a1, uint32_t a2, uint32_t a3,
                                         uint32_t b0, uint32_t b1) {
    asm volatile(
        "mma.sync.aligned.m16n8k8.row.col.f32.tf32.tf32.f32 "
        "{%0,%1,%2,%3}, {%4,%5,%6,%7}, {%8,%9}, {%0,%1,%2,%3};"
        : "+f"(c[0]), "+f"(c[1]), "+f"(c[2]), "+f"(c[3])
        : "r"(a0), "r"(a1), "r"(a2), "r"(a3), "r"(b0), "r"(b1));
}

// ---------------------------------------------------------------------------
// CSR build
// ---------------------------------------------------------------------------
__global__ void count_kernel(const int* __restrict__ ri_idx,
                             const int* __restrict__ ro_idx) {
    int t = blockIdx.x * blockDim.x + threadIdx.x;
    if (t >= BB * EE) return;
    int b = t / EE;
    atomicAdd(&g_count[(2 * b + 0) * NN + ri_idx[t]], 1);
    atomicAdd(&g_count[(2 * b + 1) * NN + ro_idx[t]], 1);
}

__global__ void __launch_bounds__(256) scan_kernel() {
    __shared__ int sh[256];
    __shared__ int s_off;
    const int bid = blockIdx.x;
    const int base = bid * SCAN_TILE + threadIdx.x * 8;

    int v[8]; int s = 0;
    #pragma unroll
    for (int j = 0; j < 8; j++) {
        int idx = base + j;
        int x = 0;
        if (idx < SEG) { x = g_count[idx]; g_count[idx] = 0; }
        v[j] = s;
        s += x;
    }
    sh[threadIdx.x] = s;
    __syncthreads();
    int acc = s;
    #pragma unroll
    for (int off = 1; off < 256; off <<= 1) {
        int t = (threadIdx.x >= off) ? sh[threadIdx.x - off] : 0;
        __syncthreads();
        acc += t;
        sh[threadIdx.x] = acc;
        __syncthreads();
    }
    const int excl_thread = acc - s;

    if (threadIdx.x == 255) {
        if (bid == 0) {
            g_scan_incl[0] = acc;
            __threadfence();
            g_scan_state[0] = 2;
            s_off = 0;
        } else {
            g_scan_agg[bid] = acc;
            __threadfence();
            g_scan_state[bid] = 1;
        }
    }
    if (bid > 0 && threadIdx.x == 0) {
        int off = 0;
        int j = bid - 1;
        while (true) {
            int st;
            do { st = g_scan_state[j]; } while (st == 0);
            __threadfence();
            if (st == 2) { off += g_scan_incl[j]; break; }
            off += g_scan_agg[j];
            j--;
        }
        s_off = off;
    }
    __syncthreads();
    const int off = s_off;
    if (bid > 0 && threadIdx.x == 255) {
        g_scan_incl[bid] = off + acc;
        __threadfence();
        g_scan_state[bid] = 2;
    }
    #pragma unroll
    for (int j = 0; j < 8; j++) {
        int idx = base + j;
        if (idx < SEG) g_start[idx] = off + excl_thread + v[j];
    }
}

__global__ void fill_kernel(const float* __restrict__ e,
                            const int* __restrict__ ri_idx,
                            const int* __restrict__ ro_idx) {
    int t = blockIdx.x * blockDim.x + threadIdx.x;
    if (t < SCAN_NB) g_scan_state[t] = 0;
    if (t >= BB * EE) return;
    int b = t / EE;
    float w = e[t];
    int ri = ri_idx[t];
    int ro = ro_idx[t];
    int s0 = (2 * b + 0) * NN + ri;
    int s1 = (2 * b + 1) * NN + ro;
    int p0 = g_start[s0] + atomicAdd(&g_fill[s0], 1);
    g_entry_src[p0] = ro;
    g_entry_w[p0]   = w;
    int p1 = g_start[s1] + atomicAdd(&g_fill[s1], 1);
    g_entry_src[p1] = ri;
    g_entry_w[p1]   = w;
}

// ---------------------------------------------------------------------------
// Gather: one warp handles TWO segments concurrently (independent load chains,
// unroll-2 each => up to 8 float4 row-loads in flight). Rounds outputs to tf32.
// ---------------------------------------------------------------------------
__device__ __forceinline__ void fma_row(float4& a0, float4& a1, float w,
                                        const float4& r0, const float4& r1) {
    a0.x = fmaf(w, r0.x, a0.x); a0.y = fmaf(w, r0.y, a0.y);
    a0.z = fmaf(w, r0.z, a0.z); a0.w = fmaf(w, r0.w, a0.w);
    a1.x = fmaf(w, r1.x, a1.x); a1.y = fmaf(w, r1.y, a1.y);
    a1.z = fmaf(w, r1.z, a1.z); a1.w = fmaf(w, r1.w, a1.w);
}

__global__ void __launch_bounds__(256) gather_kernel(const float* __restrict__ X) {
    int wt = blockIdx.x * 8 + (threadIdx.x >> 5);
    if (wt >= SEG / 2) return;
    int lane = threadIdx.x & 31;
    int segA = wt * 2;
    int segB = segA + 1;

    int arrA = segA / NN, nA = segA - arrA * NN;
    int arrB = segB / NN, nB = segB - arrB * NN;

    int sA = g_start[segA];
    int sB = g_start[segB];
    int c = 0;
    if (lane < 2) { c = g_fill[segA + lane]; g_fill[segA + lane] = 0; }
    int cA = __shfl_sync(0xffffffffu, c, 0);
    int cB = __shfl_sync(0xffffffffu, c, 1);

    const float4* XA = reinterpret_cast<const float4*>(X + (size_t)(arrA >> 1) * NN * FF);
    const float4* XB = reinterpret_cast<const float4*>(X + (size_t)(arrB >> 1) * NN * FF);

    const float4 z4 = make_float4(0.f, 0.f, 0.f, 0.f);
    float4 aA0 = z4, aA1 = z4, aB0 = z4, aB1 = z4;

    int iA = sA, eA = sA + cA;
    int iB = sB, eB = sB + cB;
    while (iA < eA || iB < eB) {
        bool pA0 = iA < eA,     pA1 = iA + 1 < eA;
        bool pB0 = iB < eB,     pB1 = iB + 1 < eB;
        float wA0 = 0.f, wA1 = 0.f, wB0 = 0.f, wB1 = 0.f;
        int   tA0 = 0, tA1 = 0, tB0 = 0, tB1 = 0;
        if (pA0) { wA0 = g_entry_w[iA];     tA0 = g_entry_src[iA]; }
        if (pA1) { wA1 = g_entry_w[iA + 1]; tA1 = g_entry_src[iA + 1]; }
        if (pB0) { wB0 = g_entry_w[iB];     tB0 = g_entry_src[iB]; }
        if (pB1) { wB1 = g_entry_w[iB + 1]; tB1 = g_entry_src[iB + 1]; }

        float4 rA00 = z4, rA01 = z4, rA10 = z4, rA11 = z4;
        float4 rB00 = z4, rB01 = z4, rB10 = z4, rB11 = z4;
        if (pA0) { const float4* p = XA + (size_t)tA0 * 64; rA00 = p[lane]; rA01 = p[lane + 32]; }
        if (pA1) { const float4* p = XA + (size_t)tA1 * 64; rA10 = p[lane]; rA11 = p[lane + 32]; }
        if (pB0) { const float4* p = XB + (size_t)tB0 * 64; rB00 = p[lane]; rB01 = p[lane + 32]; }
        if (pB1) { const float4* p = XB + (size_t)tB1 * 64; rB10 = p[lane]; rB11 = p[lane + 32]; }

        fma_row(aA0, aA1, wA0, rA00, rA01);
        fma_row(aA0, aA1, wA1, rA10, rA11);
        fma_row(aB0, aB1, wB0, rB00, rB01);
        fma_row(aB0, aB1, wB1, rB10, rB11);
        iA += 2; iB += 2;
    }

    aA0.x = tf32r(aA0.x); aA0.y = tf32r(aA0.y); aA0.z = tf32r(aA0.z); aA0.w = tf32r(aA0.w);
    aA1.x = tf32r(aA1.x); aA1.y = tf32r(aA1.y); aA1.z = tf32r(aA1.z); aA1.w = tf32r(aA1.w);
    aB0.x = tf32r(aB0.x); aB0.y = tf32r(aB0.y); aB0.z = tf32r(aB0.z); aB0.w = tf32r(aB0.w);
    aB1.x = tf32r(aB1.x); aB1.y = tf32r(aB1.y); aB1.z = tf32r(aB1.z); aB1.w = tf32r(aB1.w);

    float4* dA = reinterpret_cast<float4*>(
        g_agg + ((size_t)(arrA >> 1) * NN + nA) * 512 + (arrA & 1) * 256);
    dA[lane] = aA0; dA[lane + 32] = aA1;
    float4* dB = reinterpret_cast<float4*>(
        g_agg + ((size_t)(arrB >> 1) * NN + nB) * 512 + (arrB & 1) * 256);
    dB[lane] = aB0; dB[lane + 32] = aB1;
}

// ---------------------------------------------------------------------------
// Tensor-core GEMM (tf32 mma.sync), 4-stage cp.async, 64x64 warp tiles.
//   C[rows x 256] = tanh( A[rows x Ktot] @ W[Ktot x 256] + bias )
// Block 128(M) x 256(N) x 16(K); 256 threads = 8 warps in 2(M) x 4(N);
// warp tile 64x64 => smem fragment traffic 64KB/block-tile = 512 crossbar cyc,
// balanced against 512 MMA-issue cyc (R4's 32x64 tiles were crossbar-bound).
// smem: As[st][128][20] (frag banks 20g+tg distinct), Bs[st][16][264] (8tg+g).
// ---------------------------------------------------------------------------
#define GBM 128
#define GBK 16
#define NSTAGE 4
#define A_LD 20
#define B_LD 264
#define A_STG (GBM * A_LD)          // 2560 floats
#define B_STG (GBK * B_LD)          // 4224 floats
#define SMEM_FLOATS (NSTAGE * (A_STG + B_STG))   // 27136 floats = 108544 B

__global__ void __launch_bounds__(256, 1) mma_gemm_kernel(
    const float* __restrict__ A0, int lda0, int ka0,
    const float* __restrict__ A1, int lda1,
    const float* __restrict__ W,
    const float* __restrict__ bias,
    float* __restrict__ Cout,
    int Ktot, int rows)
{
    extern __shared__ float smem[];
    float* AsB = smem;
    float* BsB = smem + NSTAGE * A_STG;
    const uint32_t smem_u32 = (uint32_t)__cvta_generic_to_shared(smem);
    const uint32_t As_u32 = smem_u32;
    const uint32_t Bs_u32 = smem_u32 + NSTAGE * A_STG * 4;

    const int tid  = threadIdx.x;
    const int warp = tid >> 5;
    const int lane = tid & 31;
    const int g    = lane >> 2;        // 0..7
    const int tg   = lane & 3;         // 0..3
    const int wm   = warp & 1;         // 2 M-groups of 64 rows
    const int wn   = warp >> 1;        // 4 N-groups of 64 cols
    const int rowBase = blockIdx.x * GBM;

    const int ntiles = Ktot / GBK;

    float acc[4][8][4];
    #pragma unroll
    for (int mt = 0; mt < 4; mt++)
        #pragma unroll
        for (int nt = 0; nt < 8; nt++)
            #pragma unroll
            for (int r = 0; r < 4; r++) acc[mt][nt][r] = 0.f;

    // ---- tile loader: A 128x16 (2 cp16/thread), B 16x256 (4 cp16/thread) ----
    auto load_tile = [&](int st, int t) {
        const int k0 = t * GBK;
        #pragma unroll
        for (int j = 0; j < 2; j++) {
            const int u   = tid + 256 * j;
            const int row = u >> 2;
            const int kc  = (u & 3) * 4;
            const int gr  = rowBase + row;
            const float* asrc = (k0 < ka0)
                ? A0 + (size_t)gr * lda0 + (k0 + kc)
                : A1 + (size_t)gr * lda1 + (k0 - ka0 + kc);
            cp16(As_u32 + (uint32_t)((st * A_STG + row * A_LD + kc) * 4),
                 asrc, gr < rows ? 16 : 0);
        }
        #pragma unroll
        for (int j = 0; j < 4; j++) {
            const int u  = tid + 256 * j;
            const int k  = u >> 6;            // 0..15
            const int c4 = (u & 63) * 4;      // 0..252
            const float* wsrc = W + (size_t)(k0 + k) * 256 + c4;
            cp16(Bs_u32 + (uint32_t)((st * B_STG + k * B_LD + c4) * 4), wsrc, 16);
        }
    };

    #pragma unroll
    for (int t = 0; t < NSTAGE - 1; t++) {
        if (t < ntiles) load_tile(t, t);
        asm volatile("cp.async.commit_group;");
    }

    for (int t = 0; t < ntiles; t++) {
        asm volatile("cp.async.wait_group %0;" :: "n"(NSTAGE - 2));
        __syncthreads();

        const int st = t & (NSTAGE - 1);
        {
            const int tn = t + NSTAGE - 1;
            if (tn < ntiles) load_tile(tn & (NSTAGE - 1), tn);
            asm volatile("cp.async.commit_group;");
        }

        const float* Ast = AsB + st * A_STG;
        const float* Bst = BsB + st * B_STG;

        #pragma unroll
        for (int ks = 0; ks < 2; ks++) {
            const int kb = ks * 8;
            uint32_t a[4][4];
            #pragma unroll
            for (int mt = 0; mt < 4; mt++) {
                const int r = wm * 64 + mt * 16 + g;
                a[mt][0] = f2tf(Ast[(r    ) * A_LD + kb + tg    ]);
                a[mt][1] = f2tf(Ast[(r + 8) * A_LD + kb + tg    ]);
                a[mt][2] = f2tf(Ast[(r    ) * A_LD + kb + tg + 4]);
                a[mt][3] = f2tf(Ast[(r + 8) * A_LD + kb + tg + 4]);
            }
            uint32_t b[8][2];
            #pragma unroll
            for (int nt = 0; nt < 8; nt++) {
                const int n = wn * 64 + nt * 8 + g;
                b[nt][0] = f2tf(Bst[(kb + tg    ) * B_LD + n]);
                b[nt][1] = f2tf(Bst[(kb + tg + 4) * B_LD + n]);
            }
            #pragma unroll
            for (int mt = 0; mt < 4; mt++)
                #pragma unroll
                for (int nt = 0; nt < 8; nt++)
                    mma_tf32(acc[mt][nt], a[mt][0], a[mt][1], a[mt][2], a[mt][3],
                             b[nt][0], b[nt][1]);
        }
    }

    // ---- epilogue: bias + tanh, float2 stores ----
    #pragma unroll
    for (int mt = 0; mt < 4; mt++) {
        const int r0 = rowBase + wm * 64 + mt * 16 + g;
        #pragma unroll
        for (int nt = 0; nt < 8; nt++) {
            const int col = wn * 64 + nt * 8 + tg * 2;
            const float b0 = bias[col];
            const float b1 = bias[col + 1];
            if (r0 < rows) {
                float2 v;
                v.x = tanh_approx(acc[mt][nt][0] + b0);
                v.y = tanh_approx(acc[mt][nt][1] + b1);
                *reinterpret_cast<float2*>(Cout + (size_t)r0 * 256 + col) = v;
            }
            if (r0 + 8 < rows) {
                float2 v;
                v.x = tanh_approx(acc[mt][nt][2] + b0);
                v.y = tanh_approx(acc[mt][nt][3] + b1);
                *reinterpret_cast<float2*>(Cout + (size_t)(r0 + 8) * 256 + col) = v;
            }
        }
    }
}

// ---------------------------------------------------------------------------
// Launcher. Inputs (metadata order): X, e, ri_idx, ro_idx, W1, b1, W2, b2
// ---------------------------------------------------------------------------
extern "C" void kernel_launch(void* const* d_in, const int* in_sizes, int n_in,
                              void* d_out, int out_size)
{
    (void)in_sizes; (void)n_in; (void)out_size;

    const float* X  = (const float*)d_in[0];
    const float* e  = (const float*)d_in[1];
    const int*   ri = (const int*)  d_in[2];
    const int*   ro = (const int*)  d_in[3];
    const float* W1 = (const float*)d_in[4];
    const float* b1 = (const float*)d_in[5];
    const float* W2 = (const float*)d_in[6];
    const float* b2 = (const float*)d_in[7];
    float* out = (float*)d_out;

    float *agg_ptr = nullptr, *h_ptr = nullptr;
    cudaGetSymbolAddress((void**)&agg_ptr, g_agg);
    cudaGetSymbolAddress((void**)&h_ptr,   g_h);

    const int smem_bytes = SMEM_FLOATS * 4;   // 108544
    cudaFuncSetAttribute(mma_gemm_kernel,
                         cudaFuncAttributeMaxDynamicSharedMemorySize, smem_bytes);

    // --- CSR build + gather (launch #4 = gather, for profiling) ---
    count_kernel<<<(BB * EE + 255) / 256, 256>>>(ri, ro);
    scan_kernel<<<SCAN_NB, 256>>>();
    fill_kernel<<<(BB * EE + 255) / 256, 256>>>(e, ri, ro);
    gather_kernel<<<(SEG / 2 + 7) / 8, 256>>>(X);

    const int nblk = (RR + GBM - 1) / GBM;    // 782

    // --- GEMM1: h = tanh([mi|mo|X] @ W1 + b1), K = 768 ---
    mma_gemm_kernel<<<nblk, 256, smem_bytes>>>(agg_ptr, 512, 512, X, 256,
                                               W1, b1, h_ptr, KTOT, RR);

    // --- GEMM2: out = tanh(h @ W2 + b2), K = 256 ---
    mma_gemm_kernel<<<nblk, 256, smem_bytes>>>(h_ptr, 256, KTOT, nullptr, 0,
                                               W2, b2, out, 256, RR);
}

// round 7
// speedup vs baseline: 2.7816x; 1.0373x over previous
#include <cuda_runtime.h>
#include <cstdint>
#include <cstddef>

// Problem constants (fixed by the reference)
#define BB   2
#define NN   50000
#define EE   150000
#define FF   256
#define OUTD 256
#define RR   (BB * NN)       // 100000 rows
#define KTOT (3 * FF)        // 768
#define SEG  (4 * NN)        // 200000 segments
#define TOTE (4 * EE)        // 600000 CSR entries

// Scratch
__device__ float g_agg[(size_t)RR * 512];   // [r][0:256]=mi, [r][256:512]=mo

// CSR scratch (self-cleaning across calls)
__device__ int   g_count[SEG];
__device__ int   g_fill[SEG];
__device__ int   g_start[SEG];
__device__ int2  g_entry[TOTE];             // .x = src node, .y = weight bits

#define SCAN_TILE 2048
#define SCAN_NB   ((SEG + SCAN_TILE - 1) / SCAN_TILE)   // 98
__device__ volatile int g_scan_state[SCAN_NB];
__device__ int g_scan_agg[SCAN_NB];
__device__ int g_scan_incl[SCAN_NB];

// ---------------------------------------------------------------------------
// helpers
// ---------------------------------------------------------------------------
__device__ __forceinline__ uint32_t f2tf(float x) {
    uint32_t u;
    asm("cvt.rna.tf32.f32 %0, %1;" : "=r"(u) : "f"(x));
    return u;
}
__device__ __forceinline__ float tanh_approx(float x) {
    float y;
    asm("tanh.approx.f32 %0, %1;" : "=f"(y) : "f"(x));
    return y;
}
__device__ __forceinline__ void cp16(uint32_t dst, const void* src, int bytes) {
    asm volatile("cp.async.cg.shared.global [%0], [%1], 16, %2;"
                 :: "r"(dst), "l"(src), "r"(bytes));
}
__device__ __forceinline__ void mma_tf32(float c[4],
                                         uint32_t a0, uint32_t a1, uint32_t a2, uint32_t a3,
                                         uint32_t b0, uint32_t b1) {
    asm volatile(
        "mma.sync.aligned.m16n8k8.row.col.f32.tf32.tf32.f32 "
        "{%0,%1,%2,%3}, {%4,%5,%6,%7}, {%8,%9}, {%0,%1,%2,%3};"
        : "+f"(c[0]), "+f"(c[1]), "+f"(c[2]), "+f"(c[3])
        : "r"(a0), "r"(a1), "r"(a2), "r"(a3), "r"(b0), "r"(b1));
}

// ---------------------------------------------------------------------------
// CSR build
// ---------------------------------------------------------------------------
__global__ void count_kernel(const int* __restrict__ ri_idx,
                             const int* __restrict__ ro_idx) {
    int t = blockIdx.x * blockDim.x + threadIdx.x;
    if (t >= BB * EE) return;
    int b = t / EE;
    atomicAdd(&g_count[(2 * b + 0) * NN + ri_idx[t]], 1);
    atomicAdd(&g_count[(2 * b + 1) * NN + ro_idx[t]], 1);
}

__global__ void __launch_bounds__(256) scan_kernel() {
    __shared__ int sh[256];
    __shared__ int s_off;
    const int bid = blockIdx.x;
    const int base = bid * SCAN_TILE + threadIdx.x * 8;

    int v[8]; int s = 0;
    #pragma unroll
    for (int j = 0; j < 8; j++) {
        int idx = base + j;
        int x = 0;
        if (idx < SEG) { x = g_count[idx]; g_count[idx] = 0; }
        v[j] = s;
        s += x;
    }
    sh[threadIdx.x] = s;
    __syncthreads();
    int acc = s;
    #pragma unroll
    for (int off = 1; off < 256; off <<= 1) {
        int t = (threadIdx.x >= off) ? sh[threadIdx.x - off] : 0;
        __syncthreads();
        acc += t;
        sh[threadIdx.x] = acc;
        __syncthreads();
    }
    const int excl_thread = acc - s;

    if (threadIdx.x == 255) {
        if (bid == 0) {
            g_scan_incl[0] = acc;
            __threadfence();
            g_scan_state[0] = 2;
            s_off = 0;
        } else {
            g_scan_agg[bid] = acc;
            __threadfence();
            g_scan_state[bid] = 1;
        }
    }
    if (bid > 0 && threadIdx.x == 0) {
        int off = 0;
        int j = bid - 1;
        while (true) {
            int st;
            do { st = g_scan_state[j]; } while (st == 0);
            __threadfence();
            if (st == 2) { off += g_scan_incl[j]; break; }
            off += g_scan_agg[j];
            j--;
        }
        s_off = off;
    }
    __syncthreads();
    const int off = s_off;
    if (bid > 0 && threadIdx.x == 255) {
        g_scan_incl[bid] = off + acc;
        __threadfence();
        g_scan_state[bid] = 2;
    }
    #pragma unroll
    for (int j = 0; j < 8; j++) {
        int idx = base + j;
        if (idx < SEG) g_start[idx] = off + excl_thread + v[j];
    }
}

__global__ void fill_kernel(const float* __restrict__ e,
                            const int* __restrict__ ri_idx,
                            const int* __restrict__ ro_idx) {
    int t = blockIdx.x * blockDim.x + threadIdx.x;
    if (t < SCAN_NB) g_scan_state[t] = 0;
    if (t >= BB * EE) return;
    int b = t / EE;
    float w = e[t];
    int ri = ri_idx[t];
    int ro = ro_idx[t];
    int s0 = (2 * b + 0) * NN + ri;
    int s1 = (2 * b + 1) * NN + ro;
    int p0 = g_start[s0] + atomicAdd(&g_fill[s0], 1);
    g_entry[p0] = make_int2(ro, __float_as_int(w));
    int p1 = g_start[s1] + atomicAdd(&g_fill[s1], 1);
    g_entry[p1] = make_int2(ri, __float_as_int(w));
}

// ---------------------------------------------------------------------------
// Gather: one warp per TWO adjacent segments (contiguous CSR range).
// All entries preloaded in one coalesced int2 lane load + shfl broadcast ->
// row-load addresses are immediately available (no dependent entry load).
// Destination (segA vs segB) selected by masked dual-FMA.
// ---------------------------------------------------------------------------
__device__ __forceinline__ void fma_row(float4& a0, float4& a1, float w,
                                        const float4& r0, const float4& r1) {
    a0.x = fmaf(w, r0.x, a0.x); a0.y = fmaf(w, r0.y, a0.y);
    a0.z = fmaf(w, r0.z, a0.z); a0.w = fmaf(w, r0.w, a0.w);
    a1.x = fmaf(w, r1.x, a1.x); a1.y = fmaf(w, r1.y, a1.y);
    a1.z = fmaf(w, r1.z, a1.z); a1.w = fmaf(w, r1.w, a1.w);
}

__global__ void __launch_bounds__(256) gather_kernel(const float* __restrict__ X) {
    int wt = blockIdx.x * 8 + (threadIdx.x >> 5);
    if (wt >= SEG / 2) return;
    int lane = threadIdx.x & 31;

    const int segA = wt * 2;                 // segA, segA+1 share the same arr
    const int arr = segA / NN;               // (NN even => pair never crosses)
    const int n   = segA - arr * NN;
    const int b   = arr >> 1;
    const int dir = arr & 1;

    const int sA = g_start[segA];
    int c = 0;
    if (lane < 2) { c = g_fill[segA + lane]; g_fill[segA + lane] = 0; }
    const int cA = __shfl_sync(0xffffffffu, c, 0);
    const int cB = __shfl_sync(0xffffffffu, c, 1);
    const int cT = cA + cB;

    const float4* Xb = reinterpret_cast<const float4*>(X + (size_t)b * NN * FF);
    const float4 z4 = make_float4(0.f, 0.f, 0.f, 0.f);
    float4 aA0 = z4, aA1 = z4, aB0 = z4, aB1 = z4;

    for (int base = 0; base < cT; base += 32) {
        int idx = base + lane;
        int2 ev = make_int2(0, 0);
        if (idx < cT) ev = g_entry[sA + idx];
        const int lim = min(cT - base, 32);
        for (int i = 0; i < lim; i += 4) {
            #pragma unroll
            for (int j = 0; j < 4; j++) {
                if (i + j < lim) {                     // warp-uniform branch
                    int   src = __shfl_sync(0xffffffffu, ev.x, i + j);
                    float w   = __int_as_float(__shfl_sync(0xffffffffu, ev.y, i + j));
                    bool  isA = (base + i + j) < cA;
                    float wA  = isA ? w : 0.f;
                    float wB  = isA ? 0.f : w;
                    const float4* p = Xb + (size_t)src * 64;
                    float4 r0 = p[lane], r1 = p[lane + 32];
                    fma_row(aA0, aA1, wA, r0, r1);
                    fma_row(aB0, aB1, wB, r0, r1);
                }
            }
        }
    }

    float4* dA = reinterpret_cast<float4*>(
        g_agg + ((size_t)b * NN + n) * 512 + dir * 256);
    dA[lane] = aA0; dA[lane + 32] = aA1;
    float4* dB = reinterpret_cast<float4*>(
        g_agg + ((size_t)b * NN + n + 1) * 512 + dir * 256);
    dB[lane] = aB0; dB[lane + 32] = aB1;
}

// ---------------------------------------------------------------------------
// Fused 2-layer MLP (tf32 mma.sync), 3-stage cp.async, 64x64 warp tiles.
//   Phase 1: C1 = tanh([mi|mo|X] @ W1 + b1)   (K=768) -> smem Cs[128][260]
//   Phase 2: Out = tanh(C1 @ W2 + b2)          (K=256) -> global
// Block 128(M) x 256(N); 256 threads = 8 warps in 2(M) x 4(N).
// Bank checks: As frag banks 20g+tg, Bs frag banks 8tg+g, Cs frag banks
// 4g+tg (260 % 32 == 4) — all 32-distinct.
// ---------------------------------------------------------------------------
#define GBM 128
#define GBK 16
#define NST 3
#define A_LD 20
#define B_LD 264
#define C_LD 260
#define A_STG (GBM * A_LD)          // 2560 floats
#define B_STG (GBK * B_LD)          // 4224 floats
#define SMEM_FLOATS (NST * (A_STG + B_STG) + GBM * C_LD)   // 53632 = 214528 B

#define NT1 (KTOT / GBK)            // 48
#define NT2 (256  / GBK)            // 16

__global__ void __launch_bounds__(256, 1) fused_mlp_kernel(
    const float* __restrict__ Agg,
    const float* __restrict__ X,
    const float* __restrict__ W1,
    const float* __restrict__ b1,
    const float* __restrict__ W2,
    const float* __restrict__ b2,
    float* __restrict__ Out,
    int rows)
{
    extern __shared__ float smem[];
    float* AsB = smem;
    float* BsB = smem + NST * A_STG;
    float* Cs  = smem + NST * (A_STG + B_STG);
    const uint32_t smem_u = (uint32_t)__cvta_generic_to_shared(smem);
    const uint32_t As_u = smem_u;
    const uint32_t Bs_u = smem_u + NST * A_STG * 4;

    const int tid  = threadIdx.x;
    const int warp = tid >> 5;
    const int lane = tid & 31;
    const int g    = lane >> 2;
    const int tg   = lane & 3;
    const int wm   = warp & 1;
    const int wn   = warp >> 1;
    const int rowBase = blockIdx.x * GBM;

    float acc[4][8][4];
    #pragma unroll
    for (int mt = 0; mt < 4; mt++)
        #pragma unroll
        for (int nt = 0; nt < 8; nt++)
            #pragma unroll
            for (int r = 0; r < 4; r++) acc[mt][nt][r] = 0.f;

    // ---- loaders ----
    auto load_tileA = [&](int st, int t) {
        const int k0 = t * GBK;
        #pragma unroll
        for (int j = 0; j < 2; j++) {
            const int u   = tid + 256 * j;
            const int row = u >> 2;
            const int kc  = (u & 3) * 4;
            const int gr  = rowBase + row;
            const float* asrc = (k0 < 512)
                ? Agg + (size_t)gr * 512 + (k0 + kc)
                : X   + (size_t)gr * 256 + (k0 - 512 + kc);
            cp16(As_u + (uint32_t)((st * A_STG + row * A_LD + kc) * 4),
                 asrc, gr < rows ? 16 : 0);
        }
    };
    auto load_tileB = [&](int st, int t, const float* W) {
        const int k0 = t * GBK;
        #pragma unroll
        for (int j = 0; j < 4; j++) {
            const int u  = tid + 256 * j;
            const int k  = u >> 6;
            const int c4 = (u & 63) * 4;
            cp16(Bs_u + (uint32_t)((st * B_STG + k * B_LD + c4) * 4),
                 W + (size_t)(k0 + k) * 256 + c4, 16);
        }
    };

    // ================= Phase 1: K = 768 over [Agg | X] @ W1 =================
    #pragma unroll
    for (int t = 0; t < NST - 1; t++) {
        load_tileA(t, t);
        load_tileB(t, t, W1);
        asm volatile("cp.async.commit_group;");
    }

    for (int t = 0; t < NT1; t++) {
        asm volatile("cp.async.wait_group %0;" :: "n"(NST - 2));
        __syncthreads();
        const int st = t % NST;
        {
            const int tn = t + NST - 1;
            if (tn < NT1) { load_tileA(tn % NST, tn); load_tileB(tn % NST, tn, W1); }
            asm volatile("cp.async.commit_group;");
        }
        const float* Ast = AsB + st * A_STG;
        const float* Bst = BsB + st * B_STG;
        #pragma unroll
        for (int ks = 0; ks < 2; ks++) {
            const int kb = ks * 8;
            uint32_t a[4][4];
            #pragma unroll
            for (int mt = 0; mt < 4; mt++) {
                const int r = wm * 64 + mt * 16 + g;
                a[mt][0] = f2tf(Ast[(r    ) * A_LD + kb + tg    ]);
                a[mt][1] = f2tf(Ast[(r + 8) * A_LD + kb + tg    ]);
                a[mt][2] = f2tf(Ast[(r    ) * A_LD + kb + tg + 4]);
                a[mt][3] = f2tf(Ast[(r + 8) * A_LD + kb + tg + 4]);
            }
            uint32_t bfr[8][2];
            #pragma unroll
            for (int nt = 0; nt < 8; nt++) {
                const int nn = wn * 64 + nt * 8 + g;
                bfr[nt][0] = f2tf(Bst[(kb + tg    ) * B_LD + nn]);
                bfr[nt][1] = f2tf(Bst[(kb + tg + 4) * B_LD + nn]);
            }
            #pragma unroll
            for (int mt = 0; mt < 4; mt++)
                #pragma unroll
                for (int nt = 0; nt < 8; nt++)
                    mma_tf32(acc[mt][nt], a[mt][0], a[mt][1], a[mt][2], a[mt][3],
                             bfr[nt][0], bfr[nt][1]);
        }
    }

    // prefetch first two W2 tiles (stages 0,1 free: their last reads were
    // tiles 45,46, complete before the final loop barrier)
    load_tileB(0, 0, W2);
    asm volatile("cp.async.commit_group;");
    load_tileB(1, 1, W2);
    asm volatile("cp.async.commit_group;");

    // ---- epilogue 1: bias + tanh -> Cs (local rows 0..127) ----
    #pragma unroll
    for (int mt = 0; mt < 4; mt++) {
        const int r0 = wm * 64 + mt * 16 + g;
        #pragma unroll
        for (int nt = 0; nt < 8; nt++) {
            const int col = wn * 64 + nt * 8 + tg * 2;
            const float bb0 = b1[col];
            const float bb1 = b1[col + 1];
            float2 v0, v1;
            v0.x = tanh_approx(acc[mt][nt][0] + bb0);
            v0.y = tanh_approx(acc[mt][nt][1] + bb1);
            v1.x = tanh_approx(acc[mt][nt][2] + bb0);
            v1.y = tanh_approx(acc[mt][nt][3] + bb1);
            *reinterpret_cast<float2*>(&Cs[(r0    ) * C_LD + col]) = v0;
            *reinterpret_cast<float2*>(&Cs[(r0 + 8) * C_LD + col]) = v1;
            acc[mt][nt][0] = 0.f; acc[mt][nt][1] = 0.f;
            acc[mt][nt][2] = 0.f; acc[mt][nt][3] = 0.f;
        }
    }
    __syncthreads();

    // ================= Phase 2: K = 256 over Cs @ W2 =================
    for (int t = 0; t < NT2; t++) {
        asm volatile("cp.async.wait_group %0;" :: "n"(NST - 2));
        __syncthreads();
        const int st = t % NST;
        {
            const int tn = t + NST - 1;
            if (tn < NT2) load_tileB(tn % NST, tn, W2);
            asm volatile("cp.async.commit_group;");
        }
        const float* Bst = BsB + st * B_STG;
        #pragma unroll
        for (int ks = 0; ks < 2; ks++) {
            const int kb = t * GBK + ks * 8;
            uint32_t a[4][4];
            #pragma unroll
            for (int mt = 0; mt < 4; mt++) {
                const int r = wm * 64 + mt * 16 + g;
                a[mt][0] = f2tf(Cs[(r    ) * C_LD + kb + tg    ]);
                a[mt][1] = f2tf(Cs[(r + 8) * C_LD + kb + tg    ]);
                a[mt][2] = f2tf(Cs[(r    ) * C_LD + kb + tg + 4]);
                a[mt][3] = f2tf(Cs[(r + 8) * C_LD + kb + tg + 4]);
            }
            const int kbl = ks * 8;
            uint32_t bfr[8][2];
            #pragma unroll
            for (int nt = 0; nt < 8; nt++) {
                const int nn = wn * 64 + nt * 8 + g;
                bfr[nt][0] = f2tf(Bst[(kbl + tg    ) * B_LD + nn]);
                bfr[nt][1] = f2tf(Bst[(kbl + tg + 4) * B_LD + nn]);
            }
            #pragma unroll
            for (int mt = 0; mt < 4; mt++)
                #pragma unroll
                for (int nt = 0; nt < 8; nt++)
                    mma_tf32(acc[mt][nt], a[mt][0], a[mt][1], a[mt][2], a[mt][3],
                             bfr[nt][0], bfr[nt][1]);
        }
    }

    // ---- epilogue 2: bias + tanh -> global ----
    #pragma unroll
    for (int mt = 0; mt < 4; mt++) {
        const int r0 = rowBase + wm * 64 + mt * 16 + g;
        #pragma unroll
        for (int nt = 0; nt < 8; nt++) {
            const int col = wn * 64 + nt * 8 + tg * 2;
            const float bb0 = b2[col];
            const float bb1 = b2[col + 1];
            if (r0 < rows) {
                float2 v;
                v.x = tanh_approx(acc[mt][nt][0] + bb0);
                v.y = tanh_approx(acc[mt][nt][1] + bb1);
                *reinterpret_cast<float2*>(Out + (size_t)r0 * 256 + col) = v;
            }
            if (r0 + 8 < rows) {
                float2 v;
                v.x = tanh_approx(acc[mt][nt][2] + bb0);
                v.y = tanh_approx(acc[mt][nt][3] + bb1);
                *reinterpret_cast<float2*>(Out + (size_t)(r0 + 8) * 256 + col) = v;
            }
        }
    }
}

// ---------------------------------------------------------------------------
// Launcher. Inputs (metadata order): X, e, ri_idx, ro_idx, W1, b1, W2, b2
// ---------------------------------------------------------------------------
extern "C" void kernel_launch(void* const* d_in, const int* in_sizes, int n_in,
                              void* d_out, int out_size)
{
    (void)in_sizes; (void)n_in; (void)out_size;

    const float* X  = (const float*)d_in[0];
    const float* e  = (const float*)d_in[1];
    const int*   ri = (const int*)  d_in[2];
    const int*   ro = (const int*)  d_in[3];
    const float* W1 = (const float*)d_in[4];
    const float* b1 = (const float*)d_in[5];
    const float* W2 = (const float*)d_in[6];
    const float* b2 = (const float*)d_in[7];
    float* out = (float*)d_out;

    float* agg_ptr = nullptr;
    cudaGetSymbolAddress((void**)&agg_ptr, g_agg);

    const int smem_bytes = SMEM_FLOATS * 4;   // 214528
    cudaFuncSetAttribute(fused_mlp_kernel,
                         cudaFuncAttributeMaxDynamicSharedMemorySize, smem_bytes);

    // --- CSR build + gather (launch #4 = gather, for profiling) ---
    count_kernel<<<(BB * EE + 255) / 256, 256>>>(ri, ro);
    scan_kernel<<<SCAN_NB, 256>>>();
    fill_kernel<<<(BB * EE + 255) / 256, 256>>>(e, ri, ro);
    gather_kernel<<<(SEG / 2) / 8, 256>>>(X);

    // --- fused MLP: out = tanh( tanh([mi|mo|X]@W1+b1) @ W2 + b2 ) ---
    const int nblk = (RR + GBM - 1) / GBM;    // 782
    fused_mlp_kernel<<<nblk, 256, smem_bytes>>>(agg_ptr, X, W1, b1, W2, b2,
                                                out, RR);
}

// round 8
// speedup vs baseline: 3.7329x; 1.3420x over previous
#include <cuda_runtime.h>
#include <cuda_fp16.h>
#include <cstdint>
#include <cstddef>

// Problem constants (fixed by the reference)
#define BB   2
#define NN   50000
#define EE   150000
#define FF   256
#define OUTD 256
#define RR   (BB * NN)       // 100000 rows
#define KTOT (3 * FF)        // 768
#define SEG  (4 * NN)        // 200000 segments
#define TOTE (4 * EE)        // 600000 CSR entries

// fp16 operand buffers
__device__ __half g_agg_h[(size_t)RR * 512];   // [r][0:256]=mi, [r][256:512]=mo
__device__ __half g_x_h[(size_t)RR * 256];     // X in fp16
__device__ __half g_w1t[256 * KTOT];           // W1^T [n][k] fp16
__device__ __half g_w2t[256 * 256];            // W2^T [n][k] fp16

// CSR scratch (self-cleaning across calls)
__device__ int   g_count[SEG];
__device__ int   g_fill[SEG];
__device__ int   g_start[SEG];
__device__ int2  g_entry[TOTE];                // .x = src node, .y = weight bits

#define SCAN_TILE 2048
#define SCAN_NB   ((SEG + SCAN_TILE - 1) / SCAN_TILE)   // 98
__device__ volatile int g_scan_state[SCAN_NB];
__device__ int g_scan_agg[SCAN_NB];
__device__ int g_scan_incl[SCAN_NB];

// ---------------------------------------------------------------------------
// helpers
// ---------------------------------------------------------------------------
__device__ __forceinline__ float tanh_approx(float x) {
    float y;
    asm("tanh.approx.f32 %0, %1;" : "=f"(y) : "f"(x));
    return y;
}
__device__ __forceinline__ void cp16(uint32_t dst, const void* src, int bytes) {
    asm volatile("cp.async.cg.shared.global [%0], [%1], 16, %2;"
                 :: "r"(dst), "l"(src), "r"(bytes));
}
__device__ __forceinline__ uint32_t pack_h2(float lo, float hi) {
    __half2 h = __floats2half2_rn(lo, hi);    // .x = lo (low half in memory)
    return *reinterpret_cast<uint32_t*>(&h);
}
// fp16 mma with fp32 accumulate: D[16x8] += A[16x16] * B[16x8]
__device__ __forceinline__ void mma_f16(float c[4],
                                        uint32_t a0, uint32_t a1, uint32_t a2, uint32_t a3,
                                        uint32_t b0, uint32_t b1) {
    asm volatile(
        "mma.sync.aligned.m16n8k16.row.col.f32.f16.f16.f32 "
        "{%0,%1,%2,%3}, {%4,%5,%6,%7}, {%8,%9}, {%0,%1,%2,%3};"
        : "+f"(c[0]), "+f"(c[1]), "+f"(c[2]), "+f"(c[3])
        : "r"(a0), "r"(a1), "r"(a2), "r"(a3), "r"(b0), "r"(b1));
}

// ---------------------------------------------------------------------------
// CSR build
// ---------------------------------------------------------------------------
__global__ void count_kernel(const int* __restrict__ ri_idx,
                             const int* __restrict__ ro_idx) {
    int t = blockIdx.x * blockDim.x + threadIdx.x;
    if (t >= BB * EE) return;
    int b = t / EE;
    atomicAdd(&g_count[(2 * b + 0) * NN + ri_idx[t]], 1);
    atomicAdd(&g_count[(2 * b + 1) * NN + ro_idx[t]], 1);
}

__global__ void __launch_bounds__(256) scan_kernel() {
    __shared__ int sh[256];
    __shared__ int s_off;
    const int bid = blockIdx.x;
    const int base = bid * SCAN_TILE + threadIdx.x * 8;

    int v[8]; int s = 0;
    #pragma unroll
    for (int j = 0; j < 8; j++) {
        int idx = base + j;
        int x = 0;
        if (idx < SEG) { x = g_count[idx]; g_count[idx] = 0; }
        v[j] = s;
        s += x;
    }
    sh[threadIdx.x] = s;
    __syncthreads();
    int acc = s;
    #pragma unroll
    for (int off = 1; off < 256; off <<= 1) {
        int t = (threadIdx.x >= off) ? sh[threadIdx.x - off] : 0;
        __syncthreads();
        acc += t;
        sh[threadIdx.x] = acc;
        __syncthreads();
    }
    const int excl_thread = acc - s;

    if (threadIdx.x == 255) {
        if (bid == 0) {
            g_scan_incl[0] = acc;
            __threadfence();
            g_scan_state[0] = 2;
            s_off = 0;
        } else {
            g_scan_agg[bid] = acc;
            __threadfence();
            g_scan_state[bid] = 1;
        }
    }
    if (bid > 0 && threadIdx.x == 0) {
        int off = 0;
        int j = bid - 1;
        while (true) {
            int st;
            do { st = g_scan_state[j]; } while (st == 0);
            __threadfence();
            if (st == 2) { off += g_scan_incl[j]; break; }
            off += g_scan_agg[j];
            j--;
        }
        s_off = off;
    }
    __syncthreads();
    const int off = s_off;
    if (bid > 0 && threadIdx.x == 255) {
        g_scan_incl[bid] = off + acc;
        __threadfence();
        g_scan_state[bid] = 2;
    }
    #pragma unroll
    for (int j = 0; j < 8; j++) {
        int idx = base + j;
        if (idx < SEG) g_start[idx] = off + excl_thread + v[j];
    }
}

__global__ void fill_kernel(const float* __restrict__ e,
                            const int* __restrict__ ri_idx,
                            const int* __restrict__ ro_idx) {
    int t = blockIdx.x * blockDim.x + threadIdx.x;
    if (t < SCAN_NB) g_scan_state[t] = 0;
    if (t >= BB * EE) return;
    int b = t / EE;
    float w = e[t];
    int ri = ri_idx[t];
    int ro = ro_idx[t];
    int s0 = (2 * b + 0) * NN + ri;
    int s1 = (2 * b + 1) * NN + ro;
    int p0 = g_start[s0] + atomicAdd(&g_fill[s0], 1);
    g_entry[p0] = make_int2(ro, __float_as_int(w));
    int p1 = g_start[s1] + atomicAdd(&g_fill[s1], 1);
    g_entry[p1] = make_int2(ri, __float_as_int(w));
}

// ---------------------------------------------------------------------------
// Gather (R6 structure): one warp handles TWO segments via independent
// dependent-load chains, unroll-2 each (4 row-loads in flight). fp32
// accumulate, fp16 output to g_agg_h.
// ---------------------------------------------------------------------------
__device__ __forceinline__ void fma_row(float4& a0, float4& a1, float w,
                                        const float4& r0, const float4& r1) {
    a0.x = fmaf(w, r0.x, a0.x); a0.y = fmaf(w, r0.y, a0.y);
    a0.z = fmaf(w, r0.z, a0.z); a0.w = fmaf(w, r0.w, a0.w);
    a1.x = fmaf(w, r1.x, a1.x); a1.y = fmaf(w, r1.y, a1.y);
    a1.z = fmaf(w, r1.z, a1.z); a1.w = fmaf(w, r1.w, a1.w);
}

__global__ void __launch_bounds__(256) gather_kernel(const float* __restrict__ X) {
    int wt = blockIdx.x * 8 + (threadIdx.x >> 5);
    if (wt >= SEG / 2) return;
    int lane = threadIdx.x & 31;
    int segA = wt * 2;
    int segB = segA + 1;

    int arrA = segA / NN, nA = segA - arrA * NN;
    int arrB = segB / NN, nB = segB - arrB * NN;

    int sA = g_start[segA];
    int sB = g_start[segB];
    int c = 0;
    if (lane < 2) { c = g_fill[segA + lane]; g_fill[segA + lane] = 0; }
    int cA = __shfl_sync(0xffffffffu, c, 0);
    int cB = __shfl_sync(0xffffffffu, c, 1);

    const float4* XA = reinterpret_cast<const float4*>(X + (size_t)(arrA >> 1) * NN * FF);
    const float4* XB = reinterpret_cast<const float4*>(X + (size_t)(arrB >> 1) * NN * FF);

    const float4 z4 = make_float4(0.f, 0.f, 0.f, 0.f);
    float4 aA0 = z4, aA1 = z4, aB0 = z4, aB1 = z4;

    int iA = sA, eA = sA + cA;
    int iB = sB, eB = sB + cB;
    while (iA < eA || iB < eB) {
        bool pA0 = iA < eA,     pA1 = iA + 1 < eA;
        bool pB0 = iB < eB,     pB1 = iB + 1 < eB;
        int2 eA0 = make_int2(0, 0), eA1 = make_int2(0, 0);
        int2 eB0 = make_int2(0, 0), eB1 = make_int2(0, 0);
        if (pA0) eA0 = g_entry[iA];
        if (pA1) eA1 = g_entry[iA + 1];
        if (pB0) eB0 = g_entry[iB];
        if (pB1) eB1 = g_entry[iB + 1];

        float4 rA00 = z4, rA01 = z4, rA10 = z4, rA11 = z4;
        float4 rB00 = z4, rB01 = z4, rB10 = z4, rB11 = z4;
        if (pA0) { const float4* p = XA + (size_t)eA0.x * 64; rA00 = p[lane]; rA01 = p[lane + 32]; }
        if (pA1) { const float4* p = XA + (size_t)eA1.x * 64; rA10 = p[lane]; rA11 = p[lane + 32]; }
        if (pB0) { const float4* p = XB + (size_t)eB0.x * 64; rB00 = p[lane]; rB01 = p[lane + 32]; }
        if (pB1) { const float4* p = XB + (size_t)eB1.x * 64; rB10 = p[lane]; rB11 = p[lane + 32]; }

        fma_row(aA0, aA1, pA0 ? __int_as_float(eA0.y) : 0.f, rA00, rA01);
        fma_row(aA0, aA1, pA1 ? __int_as_float(eA1.y) : 0.f, rA10, rA11);
        fma_row(aB0, aB1, pB0 ? __int_as_float(eB0.y) : 0.f, rB00, rB01);
        fma_row(aB0, aB1, pB1 ? __int_as_float(eB1.y) : 0.f, rB10, rB11);
        iA += 2; iB += 2;
    }

    // pack to fp16: lane owns halves [4*lane .. 4*lane+3] and [128+4*lane ..]
    uint2 vA0 = make_uint2(pack_h2(aA0.x, aA0.y), pack_h2(aA0.z, aA0.w));
    uint2 vA1 = make_uint2(pack_h2(aA1.x, aA1.y), pack_h2(aA1.z, aA1.w));
    uint2 vB0 = make_uint2(pack_h2(aB0.x, aB0.y), pack_h2(aB0.z, aB0.w));
    uint2 vB1 = make_uint2(pack_h2(aB1.x, aB1.y), pack_h2(aB1.z, aB1.w));

    __half* dA = g_agg_h + ((size_t)(arrA >> 1) * NN + nA) * 512 + (arrA & 1) * 256;
    __half* dB = g_agg_h + ((size_t)(arrB >> 1) * NN + nB) * 512 + (arrB & 1) * 256;
    *reinterpret_cast<uint2*>(dA + 4 * lane)       = vA0;
    *reinterpret_cast<uint2*>(dA + 128 + 4 * lane) = vA1;
    *reinterpret_cast<uint2*>(dB + 4 * lane)       = vB0;
    *reinterpret_cast<uint2*>(dB + 128 + 4 * lane) = vB1;
}

// ---------------------------------------------------------------------------
// X fp32 -> fp16
// ---------------------------------------------------------------------------
__global__ void __launch_bounds__(256) convx_kernel(const float* __restrict__ X) {
    const size_t total = (size_t)RR * 256 / 8;      // 8 floats per thread-iter
    uint4* dst = reinterpret_cast<uint4*>(g_x_h);
    const float4* src = reinterpret_cast<const float4*>(X);
    for (size_t i = (size_t)blockIdx.x * blockDim.x + threadIdx.x;
         i < total; i += (size_t)gridDim.x * blockDim.x) {
        float4 f0 = src[2 * i];
        float4 f1 = src[2 * i + 1];
        uint4 o;
        o.x = pack_h2(f0.x, f0.y); o.y = pack_h2(f0.z, f0.w);
        o.z = pack_h2(f1.x, f1.y); o.w = pack_h2(f1.z, f1.w);
        dst[i] = o;
    }
}

// ---------------------------------------------------------------------------
// W[K][N] fp32 -> WT[N][K] fp16
// ---------------------------------------------------------------------------
__global__ void convw_kernel(const float* __restrict__ W, __half* __restrict__ WT,
                             int K, int N) {
    __shared__ float tile[32][33];
    int k0 = blockIdx.x * 32, n0 = blockIdx.y * 32;
    int tx = threadIdx.x, ty = threadIdx.y;
    #pragma unroll
    for (int j = 0; j < 32; j += 8)
        tile[ty + j][tx] = W[(size_t)(k0 + ty + j) * N + n0 + tx];
    __syncthreads();
    #pragma unroll
    for (int j = 0; j < 32; j += 8)
        WT[(size_t)(n0 + ty + j) * K + k0 + tx] = __float2half_rn(tile[tx][ty + j]);
}

// ---------------------------------------------------------------------------
// Fused 2-layer MLP, fp16 mma.sync m16n8k16 (fp32 accum), 4-stage cp.async.
//   Phase 1: C1 = tanh([agg|X] @ W1 + b1)  (K=768) -> smem fp16 Cs[128][280]
//   Phase 2: Out = tanh(C1 @ W2 + b2)       (K=256) -> global fp32
// Block 128(M) x 256(N) x 16(K); 256 threads = 8 warps in 2(M) x 4(N),
// warp tile 64x64, ONE m16n8k16 step per k-tile.
// Bank math (word stride must be ≡ {12,4,...} mod 32 for 12g+tg/4g+tg):
//   As: 24 halves/row -> word stride 12 -> frag banks 12g+tg distinct.
//   Bs: 24 halves/row (k-major per n)   -> 12g+tg distinct.
//   Cs: 280 halves/row -> word stride 140 ≡ 12 (mod 32) -> distinct.
// ---------------------------------------------------------------------------
#define GBM 128
#define GBK 16
#define NST 4
#define A_LDH 24
#define B_LDH 24
#define C_LDH 280
#define A_STG_B (GBM * A_LDH * 2)        // 6144 B
#define B_STG_B (256 * B_LDH * 2)        // 12288 B
#define CS_OFF  (NST * (A_STG_B + B_STG_B))              // 73728
#define SMEM_BYTES (CS_OFF + GBM * C_LDH * 2)            // 145408

#define NT1 (KTOT / GBK)            // 48
#define NT2 (256  / GBK)            // 16

__global__ void __launch_bounds__(256, 1) fused_mlp_kernel(
    const float* __restrict__ b1,
    const float* __restrict__ b2,
    float* __restrict__ Out,
    int rows)
{
    extern __shared__ char smem[];
    const uint32_t smem_u = (uint32_t)__cvta_generic_to_shared(smem);
    const uint32_t* Asw = reinterpret_cast<const uint32_t*>(smem);
    const uint32_t* Bsw = reinterpret_cast<const uint32_t*>(smem + NST * A_STG_B);
    uint32_t* Csw = reinterpret_cast<uint32_t*>(smem + CS_OFF);

    const int tid  = threadIdx.x;
    const int warp = tid >> 5;
    const int lane = tid & 31;
    const int g    = lane >> 2;
    const int tg   = lane & 3;
    const int wm   = warp & 1;
    const int wn   = warp >> 1;
    const int rowBase = blockIdx.x * GBM;

    float acc[4][8][4];
    #pragma unroll
    for (int mt = 0; mt < 4; mt++)
        #pragma unroll
        for (int nt = 0; nt < 8; nt++)
            #pragma unroll
            for (int r = 0; r < 4; r++) acc[mt][nt][r] = 0.f;

    // ---- loaders (fp16 tiles) ----
    // A: 128 rows x 16 halves = 256 x 16B chunks -> 1 cp16/thread
    auto load_tileA = [&](int st, int t) {
        const int k0 = t * GBK;
        const int row = tid >> 1;
        const int kc  = (tid & 1) * 8;          // halves
        const int gr  = rowBase + row;
        const __half* asrc = (k0 < 512)
            ? g_agg_h + (size_t)gr * 512 + (k0 + kc)
            : g_x_h   + (size_t)gr * 256 + (k0 - 512 + kc);
        cp16(smem_u + (uint32_t)(st * A_STG_B + (row * A_LDH + kc) * 2),
             asrc, gr < rows ? 16 : 0);
    };
    // B: 256 n-rows x 16 halves = 512 chunks -> 2 cp16/thread
    auto load_tileB = [&](int st, int t, const __half* WT, int ldw) {
        const int k0 = t * GBK;
        #pragma unroll
        for (int j = 0; j < 2; j++) {
            const int u  = tid + 256 * j;
            const int n  = u >> 1;
            const int kc = (u & 1) * 8;
            cp16(smem_u + (uint32_t)(NST * A_STG_B + st * B_STG_B + (n * B_LDH + kc) * 2),
                 WT + (size_t)n * ldw + k0 + kc, 16);
        }
    };

    // ================= Phase 1: K = 768, [agg|X] @ W1 =================
    #pragma unroll
    for (int t = 0; t < NST - 1; t++) {
        load_tileA(t, t);
        load_tileB(t, t, g_w1t, KTOT);
        asm volatile("cp.async.commit_group;");
    }

    for (int t = 0; t < NT1; t++) {
        asm volatile("cp.async.wait_group %0;" :: "n"(NST - 2));
        __syncthreads();
        const int st = t & (NST - 1);
        {
            const int tn = t + NST - 1;
            if (tn < NT1) { load_tileA(tn & (NST - 1), tn); load_tileB(tn & (NST - 1), tn, g_w1t, KTOT); }
            asm volatile("cp.async.commit_group;");
        }
        const uint32_t* Aw = Asw + st * (A_STG_B / 4);
        const uint32_t* Bw = Bsw + st * (B_STG_B / 4);

        uint32_t a[4][4];
        #pragma unroll
        for (int mt = 0; mt < 4; mt++) {
            const int r = wm * 64 + mt * 16 + g;
            a[mt][0] = Aw[(r    ) * 12 + tg    ];
            a[mt][1] = Aw[(r + 8) * 12 + tg    ];
            a[mt][2] = Aw[(r    ) * 12 + tg + 4];
            a[mt][3] = Aw[(r + 8) * 12 + tg + 4];
        }
        uint32_t bfr[8][2];
        #pragma unroll
        for (int nt = 0; nt < 8; nt++) {
            const int n = wn * 64 + nt * 8 + g;
            bfr[nt][0] = Bw[n * 12 + tg    ];
            bfr[nt][1] = Bw[n * 12 + tg + 4];
        }
        #pragma unroll
        for (int mt = 0; mt < 4; mt++)
            #pragma unroll
            for (int nt = 0; nt < 8; nt++)
                mma_f16(acc[mt][nt], a[mt][0], a[mt][1], a[mt][2], a[mt][3],
                        bfr[nt][0], bfr[nt][1]);
    }

    // prefetch first W2 tiles into stages 0..2 (safe: all warps past t=NT1-2)
    load_tileB(0, 0, g_w2t, 256);
    asm volatile("cp.async.commit_group;");
    load_tileB(1, 1, g_w2t, 256);
    asm volatile("cp.async.commit_group;");
    load_tileB(2, 2, g_w2t, 256);
    asm volatile("cp.async.commit_group;");

    // ---- epilogue 1: bias + tanh -> Cs fp16 ----
    #pragma unroll
    for (int mt = 0; mt < 4; mt++) {
        const int r0 = wm * 64 + mt * 16 + g;
        #pragma unroll
        for (int nt = 0; nt < 8; nt++) {
            const int col = wn * 64 + nt * 8 + tg * 2;
            const float bb0 = b1[col];
            const float bb1 = b1[col + 1];
            Csw[(r0    ) * 140 + (col >> 1)] =
                pack_h2(tanh_approx(acc[mt][nt][0] + bb0),
                        tanh_approx(acc[mt][nt][1] + bb1));
            Csw[(r0 + 8) * 140 + (col >> 1)] =
                pack_h2(tanh_approx(acc[mt][nt][2] + bb0),
                        tanh_approx(acc[mt][nt][3] + bb1));
            acc[mt][nt][0] = 0.f; acc[mt][nt][1] = 0.f;
            acc[mt][nt][2] = 0.f; acc[mt][nt][3] = 0.f;
        }
    }
    __syncthreads();

    // ================= Phase 2: K = 256, Cs @ W2 =================
    for (int t = 0; t < NT2; t++) {
        asm volatile("cp.async.wait_group %0;" :: "n"(NST - 2));
        __syncthreads();
        const int st = t & (NST - 1);
        {
            const int tn = t + NST - 1;
            if (tn < NT2) load_tileB(tn & (NST - 1), tn, g_w2t, 256);
            asm volatile("cp.async.commit_group;");
        }
        const uint32_t* Bw = Bsw + st * (B_STG_B / 4);
        const int kw = t * 8;                 // k-tile word offset in Cs row

        uint32_t a[4][4];
        #pragma unroll
        for (int mt = 0; mt < 4; mt++) {
            const int r = wm * 64 + mt * 16 + g;
            a[mt][0] = Csw[(r    ) * 140 + kw + tg    ];
            a[mt][1] = Csw[(r + 8) * 140 + kw + tg    ];
            a[mt][2] = Csw[(r    ) * 140 + kw + tg + 4];
            a[mt][3] = Csw[(r + 8) * 140 + kw + tg + 4];
        }
        uint32_t bfr[8][2];
        #pragma unroll
        for (int nt = 0; nt < 8; nt++) {
            const int n = wn * 64 + nt * 8 + g;
            bfr[nt][0] = Bw[n * 12 + tg    ];
            bfr[nt][1] = Bw[n * 12 + tg + 4];
        }
        #pragma unroll
        for (int mt = 0; mt < 4; mt++)
            #pragma unroll
            for (int nt = 0; nt < 8; nt++)
                mma_f16(acc[mt][nt], a[mt][0], a[mt][1], a[mt][2], a[mt][3],
                        bfr[nt][0], bfr[nt][1]);
    }

    // ---- epilogue 2: bias + tanh -> global fp32 ----
    #pragma unroll
    for (int mt = 0; mt < 4; mt++) {
        const int r0 = rowBase + wm * 64 + mt * 16 + g;
        #pragma unroll
        for (int nt = 0; nt < 8; nt++) {
            const int col = wn * 64 + nt * 8 + tg * 2;
            const float bb0 = b2[col];
            const float bb1 = b2[col + 1];
            if (r0 < rows) {
                float2 v;
                v.x = tanh_approx(acc[mt][nt][0] + bb0);
                v.y = tanh_approx(acc[mt][nt][1] + bb1);
                *reinterpret_cast<float2*>(Out + (size_t)r0 * 256 + col) = v;
            }
            if (r0 + 8 < rows) {
                float2 v;
                v.x = tanh_approx(acc[mt][nt][2] + bb0);
                v.y = tanh_approx(acc[mt][nt][3] + bb1);
                *reinterpret_cast<float2*>(Out + (size_t)(r0 + 8) * 256 + col) = v;
            }
        }
    }
}

// ---------------------------------------------------------------------------
// Launcher. Inputs (metadata order): X, e, ri_idx, ro_idx, W1, b1, W2, b2
// ---------------------------------------------------------------------------
extern "C" void kernel_launch(void* const* d_in, const int* in_sizes, int n_in,
                              void* d_out, int out_size)
{
    (void)in_sizes; (void)n_in; (void)out_size;

    const float* X  = (const float*)d_in[0];
    const float* e  = (const float*)d_in[1];
    const int*   ri = (const int*)  d_in[2];
    const int*   ro = (const int*)  d_in[3];
    const float* W1 = (const float*)d_in[4];
    const float* b1 = (const float*)d_in[5];
    const float* W2 = (const float*)d_in[6];
    const float* b2 = (const float*)d_in[7];
    float* out = (float*)d_out;

    __half *w1t_ptr = nullptr, *w2t_ptr = nullptr;
    cudaGetSymbolAddress((void**)&w1t_ptr, g_w1t);
    cudaGetSymbolAddress((void**)&w2t_ptr, g_w2t);

    cudaFuncSetAttribute(fused_mlp_kernel,
                         cudaFuncAttributeMaxDynamicSharedMemorySize, SMEM_BYTES);

    // --- CSR build + gather (launch #4 = gather, for profiling) ---
    count_kernel<<<(BB * EE + 255) / 256, 256>>>(ri, ro);
    scan_kernel<<<SCAN_NB, 256>>>();
    fill_kernel<<<(BB * EE + 255) / 256, 256>>>(e, ri, ro);
    gather_kernel<<<(SEG / 2) / 8, 256>>>(X);

    // --- fp16 conversions ---
    convx_kernel<<<4096, 256>>>(X);
    convw_kernel<<<dim3(KTOT / 32, 256 / 32), dim3(32, 8)>>>(W1, w1t_ptr, KTOT, 256);
    convw_kernel<<<dim3(256 / 32, 256 / 32), dim3(32, 8)>>>(W2, w2t_ptr, 256, 256);

    // --- fused MLP: out = tanh( tanh([mi|mo|X]@W1+b1) @ W2 + b2 ) ---
    const int nblk = (RR + GBM - 1) / GBM;    // 782
    fused_mlp_kernel<<<nblk, 256, SMEM_BYTES>>>(b1, b2, out, RR);
}

// round 9
// speedup vs baseline: 3.7980x; 1.0174x over previous
#include <cuda_runtime.h>
#include <cuda_fp16.h>
#include <cstdint>
#include <cstddef>

// Problem constants (fixed by the reference)
#define BB   2
#define NN   50000
#define EE   150000
#define FF   256
#define OUTD 256
#define RR   (BB * NN)       // 100000 rows
#define KTOT (3 * FF)        // 768
#define SEG  (4 * NN)        // 200000 segments
#define TOTE (4 * EE)        // 600000 CSR entries

// fp16 operand buffers
__device__ __half g_agg_h[(size_t)RR * 512];   // [r][0:256]=mi, [r][256:512]=mo
__device__ __half g_x_h[(size_t)RR * 256];     // X in fp16
__device__ __half g_w1t[256 * KTOT];           // W1^T [n][k] fp16
__device__ __half g_w2t[256 * 256];            // W2^T [n][k] fp16

// CSR scratch (self-cleaning across calls)
__device__ int   g_count[SEG];
__device__ int   g_fill[SEG];
__device__ int   g_start[SEG];
__device__ int2  g_entry[TOTE];                // .x = src node, .y = weight bits

#define SCAN_TILE 2048
#define SCAN_NB   ((SEG + SCAN_TILE - 1) / SCAN_TILE)   // 98
__device__ volatile int g_scan_state[SCAN_NB];
__device__ int g_scan_agg[SCAN_NB];
__device__ int g_scan_incl[SCAN_NB];

// ---------------------------------------------------------------------------
// helpers
// ---------------------------------------------------------------------------
__device__ __forceinline__ float tanh_approx(float x) {
    float y;
    asm("tanh.approx.f32 %0, %1;" : "=f"(y) : "f"(x));
    return y;
}
__device__ __forceinline__ void cp16(uint32_t dst, const void* src, int bytes) {
    asm volatile("cp.async.cg.shared.global [%0], [%1], 16, %2;"
                 :: "r"(dst), "l"(src), "r"(bytes));
}
__device__ __forceinline__ uint32_t pack_h2(float lo, float hi) {
    __half2 h = __floats2half2_rn(lo, hi);
    return *reinterpret_cast<uint32_t*>(&h);
}
__device__ __forceinline__ void mma_f16(float c[4],
                                        uint32_t a0, uint32_t a1, uint32_t a2, uint32_t a3,
                                        uint32_t b0, uint32_t b1) {
    asm volatile(
        "mma.sync.aligned.m16n8k16.row.col.f32.f16.f16.f32 "
        "{%0,%1,%2,%3}, {%4,%5,%6,%7}, {%8,%9}, {%0,%1,%2,%3};"
        : "+f"(c[0]), "+f"(c[1]), "+f"(c[2]), "+f"(c[3])
        : "r"(a0), "r"(a1), "r"(a2), "r"(a3), "r"(b0), "r"(b1));
}

// ---------------------------------------------------------------------------
// 1) convx + count fused (independent work; keeps gather at launch #4)
// ---------------------------------------------------------------------------
__global__ void __launch_bounds__(256) convx_count_kernel(
    const float* __restrict__ X,
    const int* __restrict__ ri_idx,
    const int* __restrict__ ro_idx)
{
    const int t = blockIdx.x * blockDim.x + threadIdx.x;
    if (t < BB * EE) {
        int b = t / EE;
        atomicAdd(&g_count[(2 * b + 0) * NN + ri_idx[t]], 1);
        atomicAdd(&g_count[(2 * b + 1) * NN + ro_idx[t]], 1);
    }
    // X fp32 -> fp16 (grid-stride)
    const size_t total = (size_t)RR * 256 / 8;
    uint4* dst = reinterpret_cast<uint4*>(g_x_h);
    const float4* src = reinterpret_cast<const float4*>(X);
    for (size_t i = (size_t)blockIdx.x * blockDim.x + threadIdx.x;
         i < total; i += (size_t)gridDim.x * blockDim.x) {
        float4 f0 = src[2 * i];
        float4 f1 = src[2 * i + 1];
        uint4 o;
        o.x = pack_h2(f0.x, f0.y); o.y = pack_h2(f0.z, f0.w);
        o.z = pack_h2(f1.x, f1.y); o.w = pack_h2(f1.z, f1.w);
        dst[i] = o;
    }
}

// ---------------------------------------------------------------------------
// 2) scan: decoupled lookback; re-zeros g_count
// ---------------------------------------------------------------------------
__global__ void __launch_bounds__(256) scan_kernel() {
    __shared__ int sh[256];
    __shared__ int s_off;
    const int bid = blockIdx.x;
    const int base = bid * SCAN_TILE + threadIdx.x * 8;

    int v[8]; int s = 0;
    #pragma unroll
    for (int j = 0; j < 8; j++) {
        int idx = base + j;
        int x = 0;
        if (idx < SEG) { x = g_count[idx]; g_count[idx] = 0; }
        v[j] = s;
        s += x;
    }
    sh[threadIdx.x] = s;
    __syncthreads();
    int acc = s;
    #pragma unroll
    for (int off = 1; off < 256; off <<= 1) {
        int t = (threadIdx.x >= off) ? sh[threadIdx.x - off] : 0;
        __syncthreads();
        acc += t;
        sh[threadIdx.x] = acc;
        __syncthreads();
    }
    const int excl_thread = acc - s;

    if (threadIdx.x == 255) {
        if (bid == 0) {
            g_scan_incl[0] = acc;
            __threadfence();
            g_scan_state[0] = 2;
            s_off = 0;
        } else {
            g_scan_agg[bid] = acc;
            __threadfence();
            g_scan_state[bid] = 1;
        }
    }
    if (bid > 0 && threadIdx.x == 0) {
        int off = 0;
        int j = bid - 1;
        while (true) {
            int st;
            do { st = g_scan_state[j]; } while (st == 0);
            __threadfence();
            if (st == 2) { off += g_scan_incl[j]; break; }
            off += g_scan_agg[j];
            j--;
        }
        s_off = off;
    }
    __syncthreads();
    const int off = s_off;
    if (bid > 0 && threadIdx.x == 255) {
        g_scan_incl[bid] = off + acc;
        __threadfence();
        g_scan_state[bid] = 2;
    }
    #pragma unroll
    for (int j = 0; j < 8; j++) {
        int idx = base + j;
        if (idx < SEG) g_start[idx] = off + excl_thread + v[j];
    }
}

// ---------------------------------------------------------------------------
// 3) fill CSR; resets scan flags
// ---------------------------------------------------------------------------
__global__ void fill_kernel(const float* __restrict__ e,
                            const int* __restrict__ ri_idx,
                            const int* __restrict__ ro_idx) {
    int t = blockIdx.x * blockDim.x + threadIdx.x;
    if (t < SCAN_NB) g_scan_state[t] = 0;
    if (t >= BB * EE) return;
    int b = t / EE;
    float w = e[t];
    int ri = ri_idx[t];
    int ro = ro_idx[t];
    int s0 = (2 * b + 0) * NN + ri;
    int s1 = (2 * b + 1) * NN + ro;
    int p0 = g_start[s0] + atomicAdd(&g_fill[s0], 1);
    g_entry[p0] = make_int2(ro, __float_as_int(w));
    int p1 = g_start[s1] + atomicAdd(&g_fill[s1], 1);
    g_entry[p1] = make_int2(ri, __float_as_int(w));
}

// ---------------------------------------------------------------------------
// 4) gather on fp16 X: one warp, two segments, unroll-2 chains.
// Row = 256 halves = 512B = ONE uint4 per lane. fp32 accumulate.
// ---------------------------------------------------------------------------
__device__ __forceinline__ void fma8(float a[8], float w, const uint4& r) {
    const __half2* h = reinterpret_cast<const __half2*>(&r);
    #pragma unroll
    for (int i = 0; i < 4; i++) {
        float2 f = __half22float2(h[i]);
        a[2 * i]     = fmaf(w, f.x, a[2 * i]);
        a[2 * i + 1] = fmaf(w, f.y, a[2 * i + 1]);
    }
}

__global__ void __launch_bounds__(256) gather_kernel() {
    int wt = blockIdx.x * 8 + (threadIdx.x >> 5);
    if (wt >= SEG / 2) return;
    int lane = threadIdx.x & 31;
    int segA = wt * 2;
    int segB = segA + 1;

    int arrA = segA / NN, nA = segA - arrA * NN;
    int arrB = segB / NN, nB = segB - arrB * NN;

    int sA = g_start[segA];
    int sB = g_start[segB];
    int c = 0;
    if (lane < 2) { c = g_fill[segA + lane]; g_fill[segA + lane] = 0; }
    int cA = __shfl_sync(0xffffffffu, c, 0);
    int cB = __shfl_sync(0xffffffffu, c, 1);

    const uint4* XA = reinterpret_cast<const uint4*>(g_x_h + (size_t)(arrA >> 1) * NN * FF);
    const uint4* XB = reinterpret_cast<const uint4*>(g_x_h + (size_t)(arrB >> 1) * NN * FF);

    float aA[8] = {0.f, 0.f, 0.f, 0.f, 0.f, 0.f, 0.f, 0.f};
    float aB[8] = {0.f, 0.f, 0.f, 0.f, 0.f, 0.f, 0.f, 0.f};
    const uint4 z4 = make_uint4(0, 0, 0, 0);

    int iA = sA, eA = sA + cA;
    int iB = sB, eB = sB + cB;
    while (iA < eA || iB < eB) {
        bool pA0 = iA < eA,     pA1 = iA + 1 < eA;
        bool pB0 = iB < eB,     pB1 = iB + 1 < eB;
        int2 eA0 = make_int2(0, 0), eA1 = make_int2(0, 0);
        int2 eB0 = make_int2(0, 0), eB1 = make_int2(0, 0);
        if (pA0) eA0 = g_entry[iA];
        if (pA1) eA1 = g_entry[iA + 1];
        if (pB0) eB0 = g_entry[iB];
        if (pB1) eB1 = g_entry[iB + 1];

        uint4 rA0 = z4, rA1 = z4, rB0 = z4, rB1 = z4;
        if (pA0) rA0 = XA[(size_t)eA0.x * 32 + lane];
        if (pA1) rA1 = XA[(size_t)eA1.x * 32 + lane];
        if (pB0) rB0 = XB[(size_t)eB0.x * 32 + lane];
        if (pB1) rB1 = XB[(size_t)eB1.x * 32 + lane];

        fma8(aA, pA0 ? __int_as_float(eA0.y) : 0.f, rA0);
        fma8(aA, pA1 ? __int_as_float(eA1.y) : 0.f, rA1);
        fma8(aB, pB0 ? __int_as_float(eB0.y) : 0.f, rB0);
        fma8(aB, pB1 ? __int_as_float(eB1.y) : 0.f, rB1);
        iA += 2; iB += 2;
    }

    uint4 oA, oB;
    oA.x = pack_h2(aA[0], aA[1]); oA.y = pack_h2(aA[2], aA[3]);
    oA.z = pack_h2(aA[4], aA[5]); oA.w = pack_h2(aA[6], aA[7]);
    oB.x = pack_h2(aB[0], aB[1]); oB.y = pack_h2(aB[2], aB[3]);
    oB.z = pack_h2(aB[4], aB[5]); oB.w = pack_h2(aB[6], aB[7]);

    __half* dA = g_agg_h + ((size_t)(arrA >> 1) * NN + nA) * 512 + (arrA & 1) * 256;
    __half* dB = g_agg_h + ((size_t)(arrB >> 1) * NN + nB) * 512 + (arrB & 1) * 256;
    *reinterpret_cast<uint4*>(dA + 8 * lane) = oA;
    *reinterpret_cast<uint4*>(dB + 8 * lane) = oB;
}

// ---------------------------------------------------------------------------
// W[K][N] fp32 -> WT[N][K] fp16
// ---------------------------------------------------------------------------
__global__ void convw_kernel(const float* __restrict__ W, __half* __restrict__ WT,
                             int K, int N) {
    __shared__ float tile[32][33];
    int k0 = blockIdx.x * 32, n0 = blockIdx.y * 32;
    int tx = threadIdx.x, ty = threadIdx.y;
    #pragma unroll
    for (int j = 0; j < 32; j += 8)
        tile[ty + j][tx] = W[(size_t)(k0 + ty + j) * N + n0 + tx];
    __syncthreads();
    #pragma unroll
    for (int j = 0; j < 32; j += 8)
        WT[(size_t)(n0 + ty + j) * K + k0 + tx] = __float2half_rn(tile[tx][ty + j]);
}

// ---------------------------------------------------------------------------
// Fused 2-layer MLP, fp16 m16n8k16, 4-stage cp.async, 512 threads.
// Block 128(M) x 256(N); 16 warps in 4(M of 32) x 4(N of 64); warp tile 32x64.
// acc = 64 regs/thread -> ~115 regs total -> 16 warps/SM (4/SMSP).
// Bank math: As/Bs word stride 12, Cs word stride 140 (≡12 mod 32) —
// fragment banks 12g+tg all-distinct.
// ---------------------------------------------------------------------------
#define GBM 128
#define GBK 16
#define NST 4
#define A_LDH 24
#define B_LDH 24
#define C_LDH 280
#define A_STG_B (GBM * A_LDH * 2)        // 6144 B
#define B_STG_B (256 * B_LDH * 2)        // 12288 B
#define CS_OFF  (NST * (A_STG_B + B_STG_B))              // 73728
#define SMEM_BYTES (CS_OFF + GBM * C_LDH * 2)            // 145408

#define NT1 (KTOT / GBK)            // 48
#define NT2 (256  / GBK)            // 16

__global__ void __launch_bounds__(512, 1) fused_mlp_kernel(
    const float* __restrict__ b1,
    const float* __restrict__ b2,
    float* __restrict__ Out,
    int rows)
{
    extern __shared__ char smem[];
    const uint32_t smem_u = (uint32_t)__cvta_generic_to_shared(smem);
    const uint32_t* Asw = reinterpret_cast<const uint32_t*>(smem);
    const uint32_t* Bsw = reinterpret_cast<const uint32_t*>(smem + NST * A_STG_B);
    uint32_t* Csw = reinterpret_cast<uint32_t*>(smem + CS_OFF);

    const int tid  = threadIdx.x;
    const int warp = tid >> 5;
    const int lane = tid & 31;
    const int g    = lane >> 2;
    const int tg   = lane & 3;
    const int wm   = warp & 3;         // M group (32 rows)
    const int wn   = warp >> 2;        // N group (64 cols)
    const int rowBase = blockIdx.x * GBM;

    float acc[2][8][4];
    #pragma unroll
    for (int mt = 0; mt < 2; mt++)
        #pragma unroll
        for (int nt = 0; nt < 8; nt++)
            #pragma unroll
            for (int r = 0; r < 4; r++) acc[mt][nt][r] = 0.f;

    // ---- loaders ----
    // A: 128 rows x 16 halves = 256 x 16B chunks -> threads 0..255
    auto load_tileA = [&](int st, int t) {
        if (tid < 256) {
            const int k0 = t * GBK;
            const int row = tid >> 1;
            const int kc  = (tid & 1) * 8;
            const int gr  = rowBase + row;
            const __half* asrc = (k0 < 512)
                ? g_agg_h + (size_t)gr * 512 + (k0 + kc)
                : g_x_h   + (size_t)gr * 256 + (k0 - 512 + kc);
            cp16(smem_u + (uint32_t)(st * A_STG_B + (row * A_LDH + kc) * 2),
                 asrc, gr < rows ? 16 : 0);
        }
    };
    // B: 256 n-rows x 16 halves = 512 chunks -> 1 per thread
    auto load_tileB = [&](int st, int t, const __half* WT, int ldw) {
        const int k0 = t * GBK;
        const int n  = tid >> 1;
        const int kc = (tid & 1) * 8;
        cp16(smem_u + (uint32_t)(NST * A_STG_B + st * B_STG_B + (n * B_LDH + kc) * 2),
             WT + (size_t)n * ldw + k0 + kc, 16);
    };

    // ================= Phase 1: K = 768, [agg|X] @ W1 =================
    #pragma unroll
    for (int t = 0; t < NST - 1; t++) {
        load_tileA(t, t);
        load_tileB(t, t, g_w1t, KTOT);
        asm volatile("cp.async.commit_group;");
    }

    for (int t = 0; t < NT1; t++) {
        asm volatile("cp.async.wait_group %0;" :: "n"(NST - 2));
        __syncthreads();
        const int st = t & (NST - 1);
        {
            const int tn = t + NST - 1;
            if (tn < NT1) { load_tileA(tn & (NST - 1), tn); load_tileB(tn & (NST - 1), tn, g_w1t, KTOT); }
            asm volatile("cp.async.commit_group;");
        }
        const uint32_t* Aw = Asw + st * (A_STG_B / 4);
        const uint32_t* Bw = Bsw + st * (B_STG_B / 4);

        uint32_t a[2][4];
        #pragma unroll
        for (int mt = 0; mt < 2; mt++) {
            const int r = wm * 32 + mt * 16 + g;
            a[mt][0] = Aw[(r    ) * 12 + tg    ];
            a[mt][1] = Aw[(r + 8) * 12 + tg    ];
            a[mt][2] = Aw[(r    ) * 12 + tg + 4];
            a[mt][3] = Aw[(r + 8) * 12 + tg + 4];
        }
        uint32_t bfr[8][2];
        #pragma unroll
        for (int nt = 0; nt < 8; nt++) {
            const int n = wn * 64 + nt * 8 + g;
            bfr[nt][0] = Bw[n * 12 + tg    ];
            bfr[nt][1] = Bw[n * 12 + tg + 4];
        }
        #pragma unroll
        for (int mt = 0; mt < 2; mt++)
            #pragma unroll
            for (int nt = 0; nt < 8; nt++)
                mma_f16(acc[mt][nt], a[mt][0], a[mt][1], a[mt][2], a[mt][3],
                        bfr[nt][0], bfr[nt][1]);
    }

    // prefetch first W2 tiles into stages 0..2
    load_tileB(0, 0, g_w2t, 256);
    asm volatile("cp.async.commit_group;");
    load_tileB(1, 1, g_w2t, 256);
    asm volatile("cp.async.commit_group;");
    load_tileB(2, 2, g_w2t, 256);
    asm volatile("cp.async.commit_group;");

    // ---- epilogue 1: bias + tanh -> Cs fp16 ----
    #pragma unroll
    for (int mt = 0; mt < 2; mt++) {
        const int r0 = wm * 32 + mt * 16 + g;
        #pragma unroll
        for (int nt = 0; nt < 8; nt++) {
            const int col = wn * 64 + nt * 8 + tg * 2;
            const float bb0 = b1[col];
            const float bb1 = b1[col + 1];
            Csw[(r0    ) * 140 + (col >> 1)] =
                pack_h2(tanh_approx(acc[mt][nt][0] + bb0),
                        tanh_approx(acc[mt][nt][1] + bb1));
            Csw[(r0 + 8) * 140 + (col >> 1)] =
                pack_h2(tanh_approx(acc[mt][nt][2] + bb0),
                        tanh_approx(acc[mt][nt][3] + bb1));
            acc[mt][nt][0] = 0.f; acc[mt][nt][1] = 0.f;
            acc[mt][nt][2] = 0.f; acc[mt][nt][3] = 0.f;
        }
    }
    __syncthreads();

    // ================= Phase 2: K = 256, Cs @ W2 =================
    for (int t = 0; t < NT2; t++) {
        asm volatile("cp.async.wait_group %0;" :: "n"(NST - 2));
        __syncthreads();
        const int st = t & (NST - 1);
        {
            const int tn = t + NST - 1;
            if (tn < NT2) load_tileB(tn & (NST - 1), tn, g_w2t, 256);
            asm volatile("cp.async.commit_group;");
        }
        const uint32_t* Bw = Bsw + st * (B_STG_B / 4);
        const int kw = t * 8;

        uint32_t a[2][4];
        #pragma unroll
        for (int mt = 0; mt < 2; mt++) {
            const int r = wm * 32 + mt * 16 + g;
            a[mt][0] = Csw[(r    ) * 140 + kw + tg    ];
            a[mt][1] = Csw[(r + 8) * 140 + kw + tg    ];
            a[mt][2] = Csw[(r    ) * 140 + kw + tg + 4];
            a[mt][3] = Csw[(r + 8) * 140 + kw + tg + 4];
        }
        uint32_t bfr[8][2];
        #pragma unroll
        for (int nt = 0; nt < 8; nt++) {
            const int n = wn * 64 + nt * 8 + g;
            bfr[nt][0] = Bw[n * 12 + tg    ];
            bfr[nt][1] = Bw[n * 12 + tg + 4];
        }
        #pragma unroll
        for (int mt = 0; mt < 2; mt++)
            #pragma unroll
            for (int nt = 0; nt < 8; nt++)
                mma_f16(acc[mt][nt], a[mt][0], a[mt][1], a[mt][2], a[mt][3],
                        bfr[nt][0], bfr[nt][1]);
    }

    // ---- epilogue 2: bias + tanh -> global fp32 ----
    #pragma unroll
    for (int mt = 0; mt < 2; mt++) {
        const int r0 = rowBase + wm * 32 + mt * 16 + g;
        #pragma unroll
        for (int nt = 0; nt < 8; nt++) {
            const int col = wn * 64 + nt * 8 + tg * 2;
            const float bb0 = b2[col];
            const float bb1 = b2[col + 1];
            if (r0 < rows) {
                float2 v;
                v.x = tanh_approx(acc[mt][nt][0] + bb0);
                v.y = tanh_approx(acc[mt][nt][1] + bb1);
                *reinterpret_cast<float2*>(Out + (size_t)r0 * 256 + col) = v;
            }
            if (r0 + 8 < rows) {
                float2 v;
                v.x = tanh_approx(acc[mt][nt][2] + bb0);
                v.y = tanh_approx(acc[mt][nt][3] + bb1);
                *reinterpret_cast<float2*>(Out + (size_t)(r0 + 8) * 256 + col) = v;
            }
        }
    }
}

// ---------------------------------------------------------------------------
// Launcher. Inputs (metadata order): X, e, ri_idx, ro_idx, W1, b1, W2, b2
// ---------------------------------------------------------------------------
extern "C" void kernel_launch(void* const* d_in, const int* in_sizes, int n_in,
                              void* d_out, int out_size)
{
    (void)in_sizes; (void)n_in; (void)out_size;

    const float* X  = (const float*)d_in[0];
    const float* e  = (const float*)d_in[1];
    const int*   ri = (const int*)  d_in[2];
    const int*   ro = (const int*)  d_in[3];
    const float* W1 = (const float*)d_in[4];
    const float* b1 = (const float*)d_in[5];
    const float* W2 = (const float*)d_in[6];
    const float* b2 = (const float*)d_in[7];
    float* out = (float*)d_out;

    __half *w1t_ptr = nullptr, *w2t_ptr = nullptr;
    cudaGetSymbolAddress((void**)&w1t_ptr, g_w1t);
    cudaGetSymbolAddress((void**)&w2t_ptr, g_w2t);

    cudaFuncSetAttribute(fused_mlp_kernel,
                         cudaFuncAttributeMaxDynamicSharedMemorySize, SMEM_BYTES);

    // 1: convx+count, 2: scan, 3: fill, 4: gather (profiled)
    convx_count_kernel<<<(BB * EE + 255) / 256, 256>>>(X, ri, ro);
    scan_kernel<<<SCAN_NB, 256>>>();
    fill_kernel<<<(BB * EE + 255) / 256, 256>>>(e, ri, ro);
    gather_kernel<<<(SEG / 2) / 8, 256>>>();

    // weight conversions
    convw_kernel<<<dim3(KTOT / 32, 256 / 32), dim3(32, 8)>>>(W1, w1t_ptr, KTOT, 256);
    convw_kernel<<<dim3(256 / 32, 256 / 32), dim3(32, 8)>>>(W2, w2t_ptr, 256, 256);

    // fused MLP
    const int nblk = (RR + GBM - 1) / GBM;    // 782
    fused_mlp_kernel<<<nblk, 512, SMEM_BYTES>>>(b1, b2, out, RR);
}

// round 10
// speedup vs baseline: 4.4229x; 1.1645x over previous
#include <cuda_runtime.h>
#include <cuda_fp16.h>
#include <cstdint>
#include <cstddef>

// Problem constants (fixed by the reference)
#define BB   2
#define NN   50000
#define EE   150000
#define FF   256
#define OUTD 256
#define RR   (BB * NN)       // 100000 rows
#define KTOT (3 * FF)        // 768
#define SEG  (4 * NN)        // 200000 segments
#define TOTE (4 * EE)        // 600000 CSR entries

#define NKB1 (KTOT / 16)     // 48 k-bricks for W1
#define NKB2 (256 / 16)      // 16 k-bricks for W2

// fp16 operand buffers
__device__ __half g_agg_h[(size_t)RR * 512];   // [r][0:256]=mi, [r][256:512]=mo
__device__ __half g_x_h[(size_t)RR * 256];     // X in fp16
// Fragment-packed weights: brick (nb, kb) = 32 lanes x 4 halves (8B/lane).
// lane (g,tg) holds W[k0+2tg][n0+g], W[k0+2tg+1][n0+g],
//                  W[k0+8+2tg][n0+g], W[k0+9+2tg][n0+g]
__device__ __half g_w1p[32 * NKB1 * 128];      // 196608 halves
__device__ __half g_w2p[32 * NKB2 * 128];      // 65536 halves

// CSR scratch (self-cleaning across calls)
__device__ int   g_count[SEG];
__device__ int   g_fill[SEG];
__device__ int   g_start[SEG];
__device__ int2  g_entry[TOTE];                // .x = src node, .y = weight bits

#define SCAN_TILE 2048
#define SCAN_NB   ((SEG + SCAN_TILE - 1) / SCAN_TILE)   // 98
__device__ volatile int g_scan_state[SCAN_NB];
__device__ int g_scan_agg[SCAN_NB];
__device__ int g_scan_incl[SCAN_NB];

// ---------------------------------------------------------------------------
// helpers
// ---------------------------------------------------------------------------
__device__ __forceinline__ float tanh_approx(float x) {
    float y;
    asm("tanh.approx.f32 %0, %1;" : "=f"(y) : "f"(x));
    return y;
}
__device__ __forceinline__ void cp16(uint32_t dst, const void* src, int bytes) {
    asm volatile("cp.async.cg.shared.global [%0], [%1], 16, %2;"
                 :: "r"(dst), "l"(src), "r"(bytes));
}
__device__ __forceinline__ uint32_t pack_h2(float lo, float hi) {
    __half2 h = __floats2half2_rn(lo, hi);
    return *reinterpret_cast<uint32_t*>(&h);
}
__device__ __forceinline__ void mma_f16(float c[4],
                                        uint32_t a0, uint32_t a1, uint32_t a2, uint32_t a3,
                                        uint32_t b0, uint32_t b1) {
    asm volatile(
        "mma.sync.aligned.m16n8k16.row.col.f32.f16.f16.f32 "
        "{%0,%1,%2,%3}, {%4,%5,%6,%7}, {%8,%9}, {%0,%1,%2,%3};"
        : "+f"(c[0]), "+f"(c[1]), "+f"(c[2]), "+f"(c[3])
        : "r"(a0), "r"(a1), "r"(a2), "r"(a3), "r"(b0), "r"(b1));
}

// ---------------------------------------------------------------------------
// 1) convx + count fused
// ---------------------------------------------------------------------------
__global__ void __launch_bounds__(256) convx_count_kernel(
    const float* __restrict__ X,
    const int* __restrict__ ri_idx,
    const int* __restrict__ ro_idx)
{
    const int t = blockIdx.x * blockDim.x + threadIdx.x;
    if (t < BB * EE) {
        int b = t / EE;
        atomicAdd(&g_count[(2 * b + 0) * NN + ri_idx[t]], 1);
        atomicAdd(&g_count[(2 * b + 1) * NN + ro_idx[t]], 1);
    }
    const size_t total = (size_t)RR * 256 / 8;
    uint4* dst = reinterpret_cast<uint4*>(g_x_h);
    const float4* src = reinterpret_cast<const float4*>(X);
    for (size_t i = (size_t)blockIdx.x * blockDim.x + threadIdx.x;
         i < total; i += (size_t)gridDim.x * blockDim.x) {
        float4 f0 = src[2 * i];
        float4 f1 = src[2 * i + 1];
        uint4 o;
        o.x = pack_h2(f0.x, f0.y); o.y = pack_h2(f0.z, f0.w);
        o.z = pack_h2(f1.x, f1.y); o.w = pack_h2(f1.z, f1.w);
        dst[i] = o;
    }
}

// ---------------------------------------------------------------------------
// 2) scan: decoupled lookback; re-zeros g_count
// ---------------------------------------------------------------------------
__global__ void __launch_bounds__(256) scan_kernel() {
    __shared__ int sh[256];
    __shared__ int s_off;
    const int bid = blockIdx.x;
    const int base = bid * SCAN_TILE + threadIdx.x * 8;

    int v[8]; int s = 0;
    #pragma unroll
    for (int j = 0; j < 8; j++) {
        int idx = base + j;
        int x = 0;
        if (idx < SEG) { x = g_count[idx]; g_count[idx] = 0; }
        v[j] = s;
        s += x;
    }
    sh[threadIdx.x] = s;
    __syncthreads();
    int acc = s;
    #pragma unroll
    for (int off = 1; off < 256; off <<= 1) {
        int t = (threadIdx.x >= off) ? sh[threadIdx.x - off] : 0;
        __syncthreads();
        acc += t;
        sh[threadIdx.x] = acc;
        __syncthreads();
    }
    const int excl_thread = acc - s;

    if (threadIdx.x == 255) {
        if (bid == 0) {
            g_scan_incl[0] = acc;
            __threadfence();
            g_scan_state[0] = 2;
            s_off = 0;
        } else {
            g_scan_agg[bid] = acc;
            __threadfence();
            g_scan_state[bid] = 1;
        }
    }
    if (bid > 0 && threadIdx.x == 0) {
        int off = 0;
        int j = bid - 1;
        while (true) {
            int st;
            do { st = g_scan_state[j]; } while (st == 0);
            __threadfence();
            if (st == 2) { off += g_scan_incl[j]; break; }
            off += g_scan_agg[j];
            j--;
        }
        s_off = off;
    }
    __syncthreads();
    const int off = s_off;
    if (bid > 0 && threadIdx.x == 255) {
        g_scan_incl[bid] = off + acc;
        __threadfence();
        g_scan_state[bid] = 2;
    }
    #pragma unroll
    for (int j = 0; j < 8; j++) {
        int idx = base + j;
        if (idx < SEG) g_start[idx] = off + excl_thread + v[j];
    }
}

// ---------------------------------------------------------------------------
// 3) fill CSR; resets scan flags
// ---------------------------------------------------------------------------
__global__ void fill_kernel(const float* __restrict__ e,
                            const int* __restrict__ ri_idx,
                            const int* __restrict__ ro_idx) {
    int t = blockIdx.x * blockDim.x + threadIdx.x;
    if (t < SCAN_NB) g_scan_state[t] = 0;
    if (t >= BB * EE) return;
    int b = t / EE;
    float w = e[t];
    int ri = ri_idx[t];
    int ro = ro_idx[t];
    int s0 = (2 * b + 0) * NN + ri;
    int s1 = (2 * b + 1) * NN + ro;
    int p0 = g_start[s0] + atomicAdd(&g_fill[s0], 1);
    g_entry[p0] = make_int2(ro, __float_as_int(w));
    int p1 = g_start[s1] + atomicAdd(&g_fill[s1], 1);
    g_entry[p1] = make_int2(ri, __float_as_int(w));
}

// ---------------------------------------------------------------------------
// 4) gather on fp16 X (unchanged from R9)
// ---------------------------------------------------------------------------
__device__ __forceinline__ void fma8(float a[8], float w, const uint4& r) {
    const __half2* h = reinterpret_cast<const __half2*>(&r);
    #pragma unroll
    for (int i = 0; i < 4; i++) {
        float2 f = __half22float2(h[i]);
        a[2 * i]     = fmaf(w, f.x, a[2 * i]);
        a[2 * i + 1] = fmaf(w, f.y, a[2 * i + 1]);
    }
}

__global__ void __launch_bounds__(256) gather_kernel() {
    int wt = blockIdx.x * 8 + (threadIdx.x >> 5);
    if (wt >= SEG / 2) return;
    int lane = threadIdx.x & 31;
    int segA = wt * 2;
    int segB = segA + 1;

    int arrA = segA / NN, nA = segA - arrA * NN;
    int arrB = segB / NN, nB = segB - arrB * NN;

    int sA = g_start[segA];
    int sB = g_start[segB];
    int c = 0;
    if (lane < 2) { c = g_fill[segA + lane]; g_fill[segA + lane] = 0; }
    int cA = __shfl_sync(0xffffffffu, c, 0);
    int cB = __shfl_sync(0xffffffffu, c, 1);

    const uint4* XA = reinterpret_cast<const uint4*>(g_x_h + (size_t)(arrA >> 1) * NN * FF);
    const uint4* XB = reinterpret_cast<const uint4*>(g_x_h + (size_t)(arrB >> 1) * NN * FF);

    float aA[8] = {0.f, 0.f, 0.f, 0.f, 0.f, 0.f, 0.f, 0.f};
    float aB[8] = {0.f, 0.f, 0.f, 0.f, 0.f, 0.f, 0.f, 0.f};
    const uint4 z4 = make_uint4(0, 0, 0, 0);

    int iA = sA, eA = sA + cA;
    int iB = sB, eB = sB + cB;
    while (iA < eA || iB < eB) {
        bool pA0 = iA < eA,     pA1 = iA + 1 < eA;
        bool pB0 = iB < eB,     pB1 = iB + 1 < eB;
        int2 eA0 = make_int2(0, 0), eA1 = make_int2(0, 0);
        int2 eB0 = make_int2(0, 0), eB1 = make_int2(0, 0);
        if (pA0) eA0 = g_entry[iA];
        if (pA1) eA1 = g_entry[iA + 1];
        if (pB0) eB0 = g_entry[iB];
        if (pB1) eB1 = g_entry[iB + 1];

        uint4 rA0 = z4, rA1 = z4, rB0 = z4, rB1 = z4;
        if (pA0) rA0 = XA[(size_t)eA0.x * 32 + lane];
        if (pA1) rA1 = XA[(size_t)eA1.x * 32 + lane];
        if (pB0) rB0 = XB[(size_t)eB0.x * 32 + lane];
        if (pB1) rB1 = XB[(size_t)eB1.x * 32 + lane];

        fma8(aA, pA0 ? __int_as_float(eA0.y) : 0.f, rA0);
        fma8(aA, pA1 ? __int_as_float(eA1.y) : 0.f, rA1);
        fma8(aB, pB0 ? __int_as_float(eB0.y) : 0.f, rB0);
        fma8(aB, pB1 ? __int_as_float(eB1.y) : 0.f, rB1);
        iA += 2; iB += 2;
    }

    uint4 oA, oB;
    oA.x = pack_h2(aA[0], aA[1]); oA.y = pack_h2(aA[2], aA[3]);
    oA.z = pack_h2(aA[4], aA[5]); oA.w = pack_h2(aA[6], aA[7]);
    oB.x = pack_h2(aB[0], aB[1]); oB.y = pack_h2(aB[2], aB[3]);
    oB.z = pack_h2(aB[4], aB[5]); oB.w = pack_h2(aB[6], aB[7]);

    __half* dA = g_agg_h + ((size_t)(arrA >> 1) * NN + nA) * 512 + (arrA & 1) * 256;
    __half* dB = g_agg_h + ((size_t)(arrB >> 1) * NN + nB) * 512 + (arrB & 1) * 256;
    *reinterpret_cast<uint4*>(dA + 8 * lane) = oA;
    *reinterpret_cast<uint4*>(dB + 8 * lane) = oB;
}

// ---------------------------------------------------------------------------
// 5/6) pack W[K][N] fp32 -> fragment bricks fp16
// one thread per (brick, lane): writes 8B
// ---------------------------------------------------------------------------
__global__ void convw_pack_kernel(const float* __restrict__ W, __half* __restrict__ out,
                                  int K, int N) {
    int idx = blockIdx.x * blockDim.x + threadIdx.x;
    int nkb = K / 16;
    int total = (N / 8) * nkb * 32;
    if (idx >= total) return;
    int lane = idx & 31;
    int brick = idx >> 5;
    int nb = brick / nkb;
    int kb = brick - nb * nkb;
    int g = lane >> 2, tg = lane & 3;
    int n = nb * 8 + g;
    int k0 = kb * 16 + 2 * tg;
    __half h[4];
    h[0] = __float2half_rn(W[(size_t)(k0    ) * N + n]);
    h[1] = __float2half_rn(W[(size_t)(k0 + 1) * N + n]);
    h[2] = __float2half_rn(W[(size_t)(k0 + 8) * N + n]);
    h[3] = __float2half_rn(W[(size_t)(k0 + 9) * N + n]);
    *reinterpret_cast<uint2*>(out + (size_t)idx * 4) = *reinterpret_cast<uint2*>(h);
}

// ---------------------------------------------------------------------------
// 7) Fused 2-layer MLP, fp16 m16n8k16, 512 threads.
// A via 4-stage cp.async smem (the only LDGSTS user: 256 ops/tile);
// B fragments fetched DIRECTLY from L2-resident fragment-packed W via one
// LDG.64 per (warp, n-brick) — no smem staging, no LDGSTS.
// Block 128(M) x 256(N); 16 warps in 4(M of 32) x 4(N of 64).
// smem: A stages (24 halves/row, frag banks 12g+tg distinct) + Cs
// (280 halves/row, word stride 140 ≡ 12 mod 32, distinct).
// ---------------------------------------------------------------------------
#define GBM 128
#define GBK 16
#define NST 4
#define A_LDH 24
#define C_LDH 280
#define A_STG_B (GBM * A_LDH * 2)                 // 6144 B
#define CS_OFF  (NST * A_STG_B)                   // 24576
#define SMEM_BYTES (CS_OFF + GBM * C_LDH * 2)     // 96256

#define NT1 NKB1            // 48
#define NT2 NKB2            // 16

__global__ void __launch_bounds__(512, 1) fused_mlp_kernel(
    const float* __restrict__ b1,
    const float* __restrict__ b2,
    float* __restrict__ Out,
    int rows)
{
    extern __shared__ char smem[];
    const uint32_t smem_u = (uint32_t)__cvta_generic_to_shared(smem);
    const uint32_t* Asw = reinterpret_cast<const uint32_t*>(smem);
    uint32_t* Csw = reinterpret_cast<uint32_t*>(smem + CS_OFF);

    const int tid  = threadIdx.x;
    const int warp = tid >> 5;
    const int lane = tid & 31;
    const int g    = lane >> 2;
    const int tg   = lane & 3;
    const int wm   = warp & 3;         // M group (32 rows)
    const int wn   = warp >> 2;        // N group (64 cols)
    const int rowBase = blockIdx.x * GBM;

    // per-warp base pointers into fragment-packed W (uint2 per lane)
    const uint2* w1b = reinterpret_cast<const uint2*>(g_w1p) + ((size_t)(wn * 8) * NT1) * 32 + lane;
    const uint2* w2b = reinterpret_cast<const uint2*>(g_w2p) + ((size_t)(wn * 8) * NT2) * 32 + lane;

    float acc[2][8][4];
    #pragma unroll
    for (int mt = 0; mt < 2; mt++)
        #pragma unroll
        for (int nt = 0; nt < 8; nt++)
            #pragma unroll
            for (int r = 0; r < 4; r++) acc[mt][nt][r] = 0.f;

    // A loader: 128 rows x 16 halves = 256 x 16B chunks -> threads 0..255
    auto load_tileA = [&](int st, int t) {
        if (tid < 256) {
            const int k0 = t * GBK;
            const int row = tid >> 1;
            const int kc  = (tid & 1) * 8;
            const int gr  = rowBase + row;
            const __half* asrc = (k0 < 512)
                ? g_agg_h + (size_t)gr * 512 + (k0 + kc)
                : g_x_h   + (size_t)gr * 256 + (k0 - 512 + kc);
            cp16(smem_u + (uint32_t)(st * A_STG_B + (row * A_LDH + kc) * 2),
                 asrc, gr < rows ? 16 : 0);
        }
    };

    // ================= Phase 1: K = 768, [agg|X] @ W1 =================
    #pragma unroll
    for (int t = 0; t < NST - 1; t++) {
        load_tileA(t, t);
        asm volatile("cp.async.commit_group;");
    }

    for (int t = 0; t < NT1; t++) {
        // B fragments for this tile: one LDG.64 per n-brick, straight from L2
        uint2 bfr[8];
        #pragma unroll
        for (int nt = 0; nt < 8; nt++)
            bfr[nt] = w1b[(size_t)(nt * NT1 + t) * 32];

        asm volatile("cp.async.wait_group %0;" :: "n"(NST - 2));
        __syncthreads();
        const int st = t & (NST - 1);
        {
            const int tn = t + NST - 1;
            if (tn < NT1) load_tileA(tn & (NST - 1), tn);
            asm volatile("cp.async.commit_group;");
        }
        const uint32_t* Aw = Asw + st * (A_STG_B / 4);

        uint32_t a[2][4];
        #pragma unroll
        for (int mt = 0; mt < 2; mt++) {
            const int r = wm * 32 + mt * 16 + g;
            a[mt][0] = Aw[(r    ) * 12 + tg    ];
            a[mt][1] = Aw[(r + 8) * 12 + tg    ];
            a[mt][2] = Aw[(r    ) * 12 + tg + 4];
            a[mt][3] = Aw[(r + 8) * 12 + tg + 4];
        }
        #pragma unroll
        for (int mt = 0; mt < 2; mt++)
            #pragma unroll
            for (int nt = 0; nt < 8; nt++)
                mma_f16(acc[mt][nt], a[mt][0], a[mt][1], a[mt][2], a[mt][3],
                        bfr[nt].x, bfr[nt].y);
    }

    // ---- epilogue 1: bias + tanh -> Cs fp16 ----
    __syncthreads();   // all A-stage reads done before Cs overlaps nothing (Cs separate) — order only
    #pragma unroll
    for (int mt = 0; mt < 2; mt++) {
        const int r0 = wm * 32 + mt * 16 + g;
        #pragma unroll
        for (int nt = 0; nt < 8; nt++) {
            const int col = wn * 64 + nt * 8 + tg * 2;
            const float bb0 = b1[col];
            const float bb1 = b1[col + 1];
            Csw[(r0    ) * 140 + (col >> 1)] =
                pack_h2(tanh_approx(acc[mt][nt][0] + bb0),
                        tanh_approx(acc[mt][nt][1] + bb1));
            Csw[(r0 + 8) * 140 + (col >> 1)] =
                pack_h2(tanh_approx(acc[mt][nt][2] + bb0),
                        tanh_approx(acc[mt][nt][3] + bb1));
            acc[mt][nt][0] = 0.f; acc[mt][nt][1] = 0.f;
            acc[mt][nt][2] = 0.f; acc[mt][nt][3] = 0.f;
        }
    }
    __syncthreads();

    // ================= Phase 2: K = 256, Cs @ W2 (no cp.async at all) ======
    for (int t = 0; t < NT2; t++) {
        uint2 bfr[8];
        #pragma unroll
        for (int nt = 0; nt < 8; nt++)
            bfr[nt] = w2b[(size_t)(nt * NT2 + t) * 32];

        const int kw = t * 8;
        uint32_t a[2][4];
        #pragma unroll
        for (int mt = 0; mt < 2; mt++) {
            const int r = wm * 32 + mt * 16 + g;
            a[mt][0] = Csw[(r    ) * 140 + kw + tg    ];
            a[mt][1] = Csw[(r + 8) * 140 + kw + tg    ];
            a[mt][2] = Csw[(r    ) * 140 + kw + tg + 4];
            a[mt][3] = Csw[(r + 8) * 140 + kw + tg + 4];
        }
        #pragma unroll
        for (int mt = 0; mt < 2; mt++)
            #pragma unroll
            for (int nt = 0; nt < 8; nt++)
                mma_f16(acc[mt][nt], a[mt][0], a[mt][1], a[mt][2], a[mt][3],
                        bfr[nt].x, bfr[nt].y);
    }

    // ---- epilogue 2: bias + tanh -> global fp32 ----
    #pragma unroll
    for (int mt = 0; mt < 2; mt++) {
        const int r0 = rowBase + wm * 32 + mt * 16 + g;
        #pragma unroll
        for (int nt = 0; nt < 8; nt++) {
            const int col = wn * 64 + nt * 8 + tg * 2;
            const float bb0 = b2[col];
            const float bb1 = b2[col + 1];
            if (r0 < rows) {
                float2 v;
                v.x = tanh_approx(acc[mt][nt][0] + bb0);
                v.y = tanh_approx(acc[mt][nt][1] + bb1);
                *reinterpret_cast<float2*>(Out + (size_t)r0 * 256 + col) = v;
            }
            if (r0 + 8 < rows) {
                float2 v;
                v.x = tanh_approx(acc[mt][nt][2] + bb0);
                v.y = tanh_approx(acc[mt][nt][3] + bb1);
                *reinterpret_cast<float2*>(Out + (size_t)(r0 + 8) * 256 + col) = v;
            }
        }
    }
}

// ---------------------------------------------------------------------------
// Launcher. Inputs (metadata order): X, e, ri_idx, ro_idx, W1, b1, W2, b2
// ---------------------------------------------------------------------------
extern "C" void kernel_launch(void* const* d_in, const int* in_sizes, int n_in,
                              void* d_out, int out_size)
{
    (void)in_sizes; (void)n_in; (void)out_size;

    const float* X  = (const float*)d_in[0];
    const float* e  = (const float*)d_in[1];
    const int*   ri = (const int*)  d_in[2];
    const int*   ro = (const int*)  d_in[3];
    const float* W1 = (const float*)d_in[4];
    const float* b1 = (const float*)d_in[5];
    const float* W2 = (const float*)d_in[6];
    const float* b2 = (const float*)d_in[7];
    float* out = (float*)d_out;

    __half *w1p_ptr = nullptr, *w2p_ptr = nullptr;
    cudaGetSymbolAddress((void**)&w1p_ptr, g_w1p);
    cudaGetSymbolAddress((void**)&w2p_ptr, g_w2p);

    cudaFuncSetAttribute(fused_mlp_kernel,
                         cudaFuncAttributeMaxDynamicSharedMemorySize, SMEM_BYTES);

    // 1: convx+count, 2: scan, 3: fill, 4: gather (profiled)
    convx_count_kernel<<<(BB * EE + 255) / 256, 256>>>(X, ri, ro);
    scan_kernel<<<SCAN_NB, 256>>>();
    fill_kernel<<<(BB * EE + 255) / 256, 256>>>(e, ri, ro);
    gather_kernel<<<(SEG / 2) / 8, 256>>>();

    // 5/6: weight fragment packing
    convw_pack_kernel<<<(32 * NKB1 * 32 + 255) / 256, 256>>>(W1, w1p_ptr, KTOT, 256);
    convw_pack_kernel<<<(32 * NKB2 * 32 + 255) / 256, 256>>>(W2, w2p_ptr, 256, 256);

    // 7: fused MLP
    const int nblk = (RR + GBM - 1) / GBM;    // 782
    fused_mlp_kernel<<<nblk, 512, SMEM_BYTES>>>(b1, b2, out, RR);
}